// round 5
// baseline (speedup 1.0000x reference)
#include <cuda_runtime.h>
#include <cuda_bf16.h>
#include <mma.h>

using namespace nvcuda;

#define B_ 64
#define S_ 48
#define E_ 512
#define H_ 512
#define G_ 2048  /* 4H */

// ---------------- scratch (static device memory; no allocations) ----------------
__device__ __align__(16) float d_G0[2 * S_ * B_ * G_];   // LN(x@Wih0^T), both dirs
__device__ __align__(16) float d_G1[2 * B_ * G_];        // LN(xc@Wih1^T)
__device__ __align__(16) float d_Zb[2 * B_ * G_];        // per-step h@Whh^T
__device__ __align__(16) double d_hf[2 * B_ * H_];       // fp64 hidden state
__device__ __align__(16) double d_cf[2 * B_ * H_];       // fp64 cell state
// tf32 hi/lo pairs stored as float
__device__ __align__(16) float d_hhi[2 * B_ * H_], d_hlo[2 * B_ * H_];
__device__ __align__(16) float d_A0hi[S_ * B_ * E_], d_A0lo[S_ * B_ * E_];
__device__ __align__(16) float d_Wih0hi[2 * G_ * E_], d_Wih0lo[2 * G_ * E_];
__device__ __align__(16) float d_Whh0hi[2 * G_ * H_], d_Whh0lo[2 * G_ * H_];
__device__ __align__(16) float d_Wih1hi[2 * G_ * 2 * H_], d_Wih1lo[2 * G_ * 2 * H_];
__device__ __align__(16) float d_Whh1hi[2 * G_ * H_], d_Whh1lo[2 * G_ * H_];
__device__ __align__(16) float d_XChi[B_ * 2 * H_], d_XClo[B_ * 2 * H_];

// ---------------- helpers ----------------
__device__ __forceinline__ float f2tf32(float x) {
    unsigned r;
    asm("cvt.rna.tf32.f32 %0, %1;" : "=r"(r) : "f"(x));
    return __uint_as_float(r);
}

// double block reduction (one value)
__device__ __forceinline__ double block_reduce_d(double a, double* buf) {
    __syncthreads();
    for (int o = 16; o > 0; o >>= 1)
        a += __shfl_down_sync(0xffffffffu, a, o);
    int w = threadIdx.x >> 5;
    if ((threadIdx.x & 31) == 0) buf[w] = a;
    __syncthreads();
    int nw = (blockDim.x + 31) >> 5;
    double s = 0.0;
    for (int i = 0; i < nw; i++) s += buf[i];
    return s;
}

__device__ __forceinline__ float sigmoidf_(float x) { return 1.f / (1.f + expf(-x)); }

// ---------------- split kernels (fp32 -> tf32 hi/lo pair, stored as float) ----------------
__global__ void split_kernel(const float* __restrict__ src, float* __restrict__ hi,
                             float* __restrict__ lo, int n) {
    int i = blockIdx.x * blockDim.x + threadIdx.x;
    if (i < n) {
        float v = src[i];
        float h = f2tf32(v);
        hi[i] = h;
        lo[i] = f2tf32(v - h);
    }
}

// x[b][s][e] -> A[(s*B+b)][e] with tf32 split
__global__ void split_x_kernel(const float* __restrict__ x, float* __restrict__ hi,
                               float* __restrict__ lo) {
    int i = blockIdx.x * blockDim.x + threadIdx.x;
    if (i < S_ * B_ * E_) {
        int e = i % E_;
        int r = i / E_;
        int s = r / B_;
        int b = r % B_;
        float v = x[((size_t)b * S_ + s) * E_ + e];
        float h = f2tf32(v);
        hi[i] = h;
        lo[i] = f2tf32(v - h);
    }
}

__global__ void init_hc_kernel(double* __restrict__ h, double* __restrict__ c,
                               float* __restrict__ hhi, float* __restrict__ hlo) {
    int i = blockIdx.x * blockDim.x + threadIdx.x;
    if (i < 2 * B_ * H_) {
        h[i] = 0.0; c[i] = 0.0;
        hhi[i] = 0.f; hlo[i] = 0.f;
    }
}

// xc[b][k] = concat(h_dir0[b], h_dir1[b]) tf32 hi/lo
__global__ void build_xc_kernel(const float* __restrict__ hhi, const float* __restrict__ hlo,
                                float* __restrict__ xchi, float* __restrict__ xclo) {
    int i = blockIdx.x * blockDim.x + threadIdx.x;
    if (i < B_ * 2 * H_) {
        int k = i % (2 * H_);
        int b = i / (2 * H_);
        int d = k / H_;
        int j = k % H_;
        size_t src = (size_t)(d * B_ + b) * H_ + j;
        xchi[i] = hhi[src];
        xclo[i] = hlo[src];
    }
}

// ---------------- 3-term split-tf32 GEMM with segregated accumulators ----------------
// C[m][n] = sum_k A[m][k]*W[n][k];  value = hi + lo (tf32 pair)
// main term hi*hi kept in TWO K-chunk accumulators (halved rounding chain);
// cross terms hi*lo + lo*hi in a separate accumulator; combined in double.
template <int BM, int BN>
__global__ void __launch_bounds__(256, 1)
gemm3_tf32_kernel(const float* __restrict__ Ahi, const float* __restrict__ Alo,
                  const float* __restrict__ Whi, const float* __restrict__ Wlo,
                  float* __restrict__ C, int M, int N, int K,
                  long aBatch, long wBatch, long cBatch) {
    constexpr int BK = 16;
    constexpr int LDS = BK + 4;  // 20 floats = 80B row stride
    const int z = blockIdx.z;
    Ahi += (size_t)z * aBatch; Alo += (size_t)z * aBatch;
    Whi += (size_t)z * wBatch; Wlo += (size_t)z * wBatch;
    C += (size_t)z * cBatch;
    const int m0 = blockIdx.y * BM, n0 = blockIdx.x * BN;
    const int tid = threadIdx.x;

    __shared__ __align__(16) float sAh[BM][LDS];
    __shared__ __align__(16) float sAl[BM][LDS];
    __shared__ __align__(16) float sBh[BN][LDS];
    __shared__ __align__(16) float sBl[BN][LDS];

    // 8 warps: (BM/32) x (BN/32) = 2 x 4; warp tile 32x32 -> acc frag [2][2]
    wmma::fragment<wmma::accumulator, 16, 16, 8, float> accM0[2][2], accM1[2][2], accX[2][2];
#pragma unroll
    for (int i = 0; i < 2; i++)
#pragma unroll
        for (int j = 0; j < 2; j++) {
            wmma::fill_fragment(accM0[i][j], 0.f);
            wmma::fill_fragment(accM1[i][j], 0.f);
            wmma::fill_fragment(accX[i][j], 0.f);
        }

    const int wid = tid >> 5;
    const int wm = wid >> 2;       // 0..1 -> 32-row slice
    const int wn = wid & 3;        // 0..3 -> 32-col slice
    const int Khalf = K >> 1;

    for (int k0 = 0; k0 < K; k0 += BK) {
#pragma unroll
        for (int i = tid; i < BM * (BK / 4); i += 256) {
            int r = i / (BK / 4), q = i % (BK / 4);
            size_t g = (size_t)(m0 + r) * K + k0 + q * 4;
            *(float4*)&sAh[r][q * 4] = *(const float4*)(Ahi + g);
            *(float4*)&sAl[r][q * 4] = *(const float4*)(Alo + g);
        }
#pragma unroll
        for (int i = tid; i < BN * (BK / 4); i += 256) {
            int r = i / (BK / 4), q = i % (BK / 4);
            size_t g = (size_t)(n0 + r) * K + k0 + q * 4;
            *(float4*)&sBh[r][q * 4] = *(const float4*)(Whi + g);
            *(float4*)&sBl[r][q * 4] = *(const float4*)(Wlo + g);
        }
        __syncthreads();
        const bool firstHalf = (k0 < Khalf);
#pragma unroll
        for (int kk = 0; kk < BK; kk += 8) {
            wmma::fragment<wmma::matrix_a, 16, 16, 8, wmma::precision::tf32, wmma::row_major> ah[2], al[2];
            wmma::fragment<wmma::matrix_b, 16, 16, 8, wmma::precision::tf32, wmma::col_major> bh[2], bl[2];
#pragma unroll
            for (int i = 0; i < 2; i++) {
                wmma::load_matrix_sync(ah[i], &sAh[wm * 32 + i * 16][kk], LDS);
                wmma::load_matrix_sync(al[i], &sAl[wm * 32 + i * 16][kk], LDS);
                wmma::load_matrix_sync(bh[i], &sBh[wn * 32 + i * 16][kk], LDS);
                wmma::load_matrix_sync(bl[i], &sBl[wn * 32 + i * 16][kk], LDS);
            }
            if (firstHalf) {
#pragma unroll
                for (int i = 0; i < 2; i++)
#pragma unroll
                    for (int j = 0; j < 2; j++)
                        wmma::mma_sync(accM0[i][j], ah[i], bh[j], accM0[i][j]);
            } else {
#pragma unroll
                for (int i = 0; i < 2; i++)
#pragma unroll
                    for (int j = 0; j < 2; j++)
                        wmma::mma_sync(accM1[i][j], ah[i], bh[j], accM1[i][j]);
            }
#pragma unroll
            for (int i = 0; i < 2; i++)
#pragma unroll
                for (int j = 0; j < 2; j++) {
                    wmma::mma_sync(accX[i][j], ah[i], bl[j], accX[i][j]);
                    wmma::mma_sync(accX[i][j], al[i], bh[j], accX[i][j]);
                }
        }
        __syncthreads();
    }
    // combine in double, store fp32
#pragma unroll
    for (int i = 0; i < 2; i++)
#pragma unroll
        for (int j = 0; j < 2; j++) {
#pragma unroll
            for (int e = 0; e < accM0[i][j].num_elements; e++)
                accM0[i][j].x[e] = (float)(((double)accM0[i][j].x[e] + (double)accM1[i][j].x[e])
                                           + (double)accX[i][j].x[e]);
            wmma::store_matrix_sync(&C[(size_t)(m0 + wm * 32 + i * 16) * N + n0 + wn * 32 + j * 16],
                                    accM0[i][j], N, wmma::mem_row_major);
        }
}

// ---------------- row LayerNorm (in-place, width 2048, two-pass fp64 stats) ----------------
__global__ void ln_rows_kernel(float* __restrict__ data, const float* __restrict__ gamma,
                               const float* __restrict__ beta, int rowsPerDir) {
    __shared__ double red[8];
    const int width = G_;
    long row = blockIdx.x;
    int d = (int)(row / rowsPerDir);
    float* p = data + row * (long)width;
    const int tid = threadIdx.x;
    float v[8];
    double s = 0.0;
#pragma unroll
    for (int q = 0; q < 8; q++) {
        v[q] = p[tid + q * 256];
        s += (double)v[q];
    }
    s = block_reduce_d(s, red);
    double mu = s / width;
    double sq = 0.0;
#pragma unroll
    for (int q = 0; q < 8; q++) {
        double dv = (double)v[q] - mu;
        sq += dv * dv;
    }
    sq = block_reduce_d(sq, red);
    double rstd = rsqrt(sq / width + 1e-5);
    const float* g = gamma + (size_t)d * width;
    const float* be = beta + (size_t)d * width;
#pragma unroll
    for (int q = 0; q < 8; q++) {
        int j = tid + q * 256;
        p[j] = (float)(((double)v[q] - mu) * rstd * (double)g[j] + (double)be[j]);
    }
}

// ---------------- fused LSTM cell (fp64 internals): LN(z) + gates + c + LN(c) + h ----------------
// grid: (B_, 2); block: 256
__global__ void cell_kernel(const float* __restrict__ Z, const float* __restrict__ gih,
                            int gihTimeStride, long gihDirStride,
                            const float* __restrict__ g_hh, const float* __restrict__ b_hh,
                            const float* __restrict__ g_ho, const float* __restrict__ b_ho,
                            double* __restrict__ c, double* __restrict__ h,
                            float* __restrict__ hhi, float* __restrict__ hlo,
                            int t, int writeOut, float* __restrict__ out) {
    __shared__ double red[8];
    const int d = blockIdx.y, b = blockIdx.x, tid = threadIdx.x;
    const float* z = Z + (size_t)(d * B_ + b) * G_;
    const int tt = (d == 0) ? t : (S_ - 1 - t);
    const float* gi = gih + (size_t)d * gihDirStride + (size_t)tt * gihTimeStride + (size_t)b * G_;

    // cache z (8 values per thread), two-pass LN stats in fp64
    float zr[8];
    double s = 0.0;
#pragma unroll
    for (int q = 0; q < 8; q++) {
        zr[q] = z[tid + q * 256];
        s += (double)zr[q];
    }
    s = block_reduce_d(s, red);
    double mu = s / G_;
    double sq = 0.0;
#pragma unroll
    for (int q = 0; q < 8; q++) {
        double dv = (double)zr[q] - mu;
        sq += dv * dv;
    }
    sq = block_reduce_d(sq, red);
    double rstd = rsqrt(sq / G_ + 1e-5);

    // gates + cell update (fp64 combine; transcendentals fp32)
    const float* ghh = g_hh + (size_t)d * G_;
    const float* bhh = b_hh + (size_t)d * G_;
    double cn_st[2], o_st[2];
    double s2 = 0.0;
#pragma unroll
    for (int cnt = 0; cnt < 2; cnt++) {
        int j = tid + cnt * 256;
        // zr index for gate-offset j + q*H_: zreg slot = cnt + 2*gate
        double ai = (double)gi[j]            + ((double)zr[cnt]     - mu) * rstd * (double)ghh[j]            + (double)bhh[j];
        double af = (double)gi[j + H_]       + ((double)zr[cnt + 2] - mu) * rstd * (double)ghh[j + H_]       + (double)bhh[j + H_];
        double ao = (double)gi[j + 2 * H_]   + ((double)zr[cnt + 4] - mu) * rstd * (double)ghh[j + 2 * H_]   + (double)bhh[j + 2 * H_];
        double ag = (double)gi[j + 3 * H_]   + ((double)zr[cnt + 6] - mu) * rstd * (double)ghh[j + 3 * H_]   + (double)bhh[j + 3 * H_];
        double ig = (double)sigmoidf_((float)ai);
        double fg = (double)sigmoidf_((float)af);
        double og = (double)sigmoidf_((float)ao);
        double gg = (double)tanhf((float)ag);
        size_t ci = (size_t)(d * B_ + b) * H_ + j;
        double cn = fg * c[ci] + ig * gg;
        c[ci] = cn;
        cn_st[cnt] = cn;
        o_st[cnt] = og;
        s2 += cn;
    }
    s2 = block_reduce_d(s2, red);
    double muc = s2 / H_;
    double sq2 = 0.0;
#pragma unroll
    for (int cnt = 0; cnt < 2; cnt++) {
        double dv = cn_st[cnt] - muc;
        sq2 += dv * dv;
    }
    sq2 = block_reduce_d(sq2, red);
    double rstdc = rsqrt(sq2 / H_ + 1e-5);

    // h = o * tanh(LN(c)); split to tf32 pair for next step's GEMM
    const float* gho = g_ho + (size_t)d * H_;
    const float* bho = b_ho + (size_t)d * H_;
#pragma unroll
    for (int cnt = 0; cnt < 2; cnt++) {
        int j = tid + cnt * 256;
        double lnc = (cn_st[cnt] - muc) * rstdc * (double)gho[j] + (double)bho[j];
        double hn = o_st[cnt] * (double)tanhf((float)lnc);
        size_t hi_ = (size_t)(d * B_ + b) * H_ + j;
        h[hi_] = hn;
        float hv = (float)hn;
        float hb = f2tf32(hv);
        hhi[hi_] = hb;
        hlo[hi_] = f2tf32(hv - hb);
        if (writeOut) out[(size_t)b * (2 * H_) + (size_t)d * H_ + j] = (float)hn;
    }
}

// ---------------- host orchestration ----------------
extern "C" void kernel_launch(void* const* d_in, const int* in_sizes, int n_in,
                              void* d_out, int out_size) {
    const float* x = (const float*)d_in[0];
    // d_in[1] = text_length (unused)
    const float* w_ih0 = (const float*)d_in[2];
    const float* w_hh0 = (const float*)d_in[3];
    const float* ln_ih0_g = (const float*)d_in[4];
    const float* ln_ih0_b = (const float*)d_in[5];
    const float* ln_hh0_g = (const float*)d_in[6];
    const float* ln_hh0_b = (const float*)d_in[7];
    const float* ln_ho0_g = (const float*)d_in[8];
    const float* ln_ho0_b = (const float*)d_in[9];
    const float* w_ih1 = (const float*)d_in[10];
    const float* w_hh1 = (const float*)d_in[11];
    const float* ln_ih1_g = (const float*)d_in[12];
    const float* ln_ih1_b = (const float*)d_in[13];
    const float* ln_hh1_g = (const float*)d_in[14];
    const float* ln_hh1_b = (const float*)d_in[15];
    const float* ln_ho1_g = (const float*)d_in[16];
    const float* ln_ho1_b = (const float*)d_in[17];
    float* out = (float*)d_out;

    float *G0, *G1, *Z;
    double *h, *c;
    float *hhi, *hlo, *A0hi, *A0lo, *Wih0hi, *Wih0lo, *Whh0hi, *Whh0lo;
    float *Wih1hi, *Wih1lo, *Whh1hi, *Whh1lo, *XChi, *XClo;
    cudaGetSymbolAddress((void**)&G0, d_G0);
    cudaGetSymbolAddress((void**)&G1, d_G1);
    cudaGetSymbolAddress((void**)&Z, d_Zb);
    cudaGetSymbolAddress((void**)&h, d_hf);
    cudaGetSymbolAddress((void**)&c, d_cf);
    cudaGetSymbolAddress((void**)&hhi, d_hhi);
    cudaGetSymbolAddress((void**)&hlo, d_hlo);
    cudaGetSymbolAddress((void**)&A0hi, d_A0hi);
    cudaGetSymbolAddress((void**)&A0lo, d_A0lo);
    cudaGetSymbolAddress((void**)&Wih0hi, d_Wih0hi);
    cudaGetSymbolAddress((void**)&Wih0lo, d_Wih0lo);
    cudaGetSymbolAddress((void**)&Whh0hi, d_Whh0hi);
    cudaGetSymbolAddress((void**)&Whh0lo, d_Whh0lo);
    cudaGetSymbolAddress((void**)&Wih1hi, d_Wih1hi);
    cudaGetSymbolAddress((void**)&Wih1lo, d_Wih1lo);
    cudaGetSymbolAddress((void**)&Whh1hi, d_Whh1hi);
    cudaGetSymbolAddress((void**)&Whh1lo, d_Whh1lo);
    cudaGetSymbolAddress((void**)&XChi, d_XChi);
    cudaGetSymbolAddress((void**)&XClo, d_XClo);

    int n;
    n = S_ * B_ * E_;
    split_x_kernel<<<(n + 255) / 256, 256>>>(x, A0hi, A0lo);
    n = 2 * G_ * E_;
    split_kernel<<<(n + 255) / 256, 256>>>(w_ih0, Wih0hi, Wih0lo, n);
    n = 2 * G_ * H_;
    split_kernel<<<(n + 255) / 256, 256>>>(w_hh0, Whh0hi, Whh0lo, n);
    n = 2 * G_ * 2 * H_;
    split_kernel<<<(n + 255) / 256, 256>>>(w_ih1, Wih1hi, Wih1lo, n);
    n = 2 * G_ * H_;
    split_kernel<<<(n + 255) / 256, 256>>>(w_hh1, Whh1hi, Whh1lo, n);

    // layer-0 input projection: [3072,512] x [2048,512]^T per dir
    {
        dim3 grid(G_ / 128, (S_ * B_) / 64, 2);
        gemm3_tf32_kernel<64, 128><<<grid, 256>>>(A0hi, A0lo, Wih0hi, Wih0lo, G0,
                                                  S_ * B_, G_, E_,
                                                  0L, (long)G_ * E_, (long)S_ * B_ * G_);
    }
    ln_rows_kernel<<<2 * S_ * B_, 256>>>(G0, ln_ih0_g, ln_ih0_b, S_ * B_);

    // ---- layer 0 scan ----
    init_hc_kernel<<<(2 * B_ * H_ + 255) / 256, 256>>>(h, c, hhi, hlo);
    for (int t = 0; t < S_; t++) {
        dim3 grid(G_ / 128, 1, 2);
        gemm3_tf32_kernel<64, 128><<<grid, 256>>>(hhi, hlo, Whh0hi, Whh0lo, Z,
                                                  B_, G_, H_,
                                                  (long)B_ * H_, (long)G_ * H_, (long)B_ * G_);
        dim3 cg(B_, 2);
        cell_kernel<<<cg, 256>>>(Z, G0, B_ * G_, (long)S_ * B_ * G_,
                                 ln_hh0_g, ln_hh0_b, ln_ho0_g, ln_ho0_b,
                                 c, h, hhi, hlo, t, 0, out);
    }

    // ---- layer 1 input (constant over time due to aliasing bug) ----
    build_xc_kernel<<<(B_ * 2 * H_ + 255) / 256, 256>>>(hhi, hlo, XChi, XClo);
    {
        dim3 grid(G_ / 128, 1, 2);
        gemm3_tf32_kernel<64, 128><<<grid, 256>>>(XChi, XClo, Wih1hi, Wih1lo, G1,
                                                  B_, G_, 2 * H_,
                                                  0L, (long)G_ * 2 * H_, (long)B_ * G_);
    }
    ln_rows_kernel<<<2 * B_, 256>>>(G1, ln_ih1_g, ln_ih1_b, B_);

    // ---- layer 1 scan ----
    init_hc_kernel<<<(2 * B_ * H_ + 255) / 256, 256>>>(h, c, hhi, hlo);
    for (int t = 0; t < S_; t++) {
        dim3 grid(G_ / 128, 1, 2);
        gemm3_tf32_kernel<64, 128><<<grid, 256>>>(hhi, hlo, Whh1hi, Whh1lo, Z,
                                                  B_, G_, H_,
                                                  (long)B_ * H_, (long)G_ * H_, (long)B_ * G_);
        dim3 cg(B_, 2);
        cell_kernel<<<cg, 256>>>(Z, G1, 0, (long)B_ * G_,
                                 ln_hh1_g, ln_hh1_b, ln_ho1_g, ln_ho1_b,
                                 c, h, hhi, hlo, t, (t == S_ - 1) ? 1 : 0, out);
    }
}

// round 6
// speedup vs baseline: 1.5184x; 1.5184x over previous
#include <cuda_runtime.h>
#include <cuda_bf16.h>
#include <mma.h>

using namespace nvcuda;

#define B_ 64
#define S_ 48
#define E_ 512
#define H_ 512
#define G_ 2048  /* 4H */
#define NCTA 128

// ---------------- scratch (static device memory; no allocations) ----------------
__device__ __align__(16) float d_G0[2 * S_ * B_ * G_];   // LN(x@Wih0^T), both dirs
__device__ __align__(16) float d_G1[2 * B_ * G_];        // LN(xc@Wih1^T)
__device__ __align__(16) float d_Zb[2 * B_ * G_];        // per-step h@Whh^T
// tf32 hi/lo pairs stored as float
__device__ __align__(16) float d_hhi[2 * B_ * H_], d_hlo[2 * B_ * H_];
__device__ __align__(16) float d_A0hi[S_ * B_ * E_], d_A0lo[S_ * B_ * E_];
__device__ __align__(16) float d_Wih0hi[2 * G_ * E_], d_Wih0lo[2 * G_ * E_];
__device__ __align__(16) float d_Whh0hi[2 * G_ * H_], d_Whh0lo[2 * G_ * H_];
__device__ __align__(16) float d_Wih1hi[2 * G_ * 2 * H_], d_Wih1lo[2 * G_ * 2 * H_];
__device__ __align__(16) float d_Whh1hi[2 * G_ * H_], d_Whh1lo[2 * G_ * H_];
__device__ __align__(16) float d_XChi[B_ * 2 * H_], d_XClo[B_ * 2 * H_];

// grid-barrier state (returns to initial modulo gen counter; gen is monotonic)
__device__ unsigned d_bar_count = 0;
__device__ unsigned d_bar_gen = 0;

// ---------------- helpers ----------------
__device__ __forceinline__ float f2tf32(float x) {
    unsigned r;
    asm("cvt.rna.tf32.f32 %0, %1;" : "=r"(r) : "f"(x));
    return __uint_as_float(r);
}

__device__ __forceinline__ double block_reduce_d(double a, double* buf) {
    __syncthreads();
    for (int o = 16; o > 0; o >>= 1)
        a += __shfl_down_sync(0xffffffffu, a, o);
    int w = threadIdx.x >> 5;
    if ((threadIdx.x & 31) == 0) buf[w] = a;
    __syncthreads();
    int nw = (blockDim.x + 31) >> 5;
    double s = 0.0;
    for (int i = 0; i < nw; i++) s += buf[i];
    return s;
}

__device__ __forceinline__ float sigmoidf_(float x) { return 1.f / (1.f + expf(-x)); }

// all-threads fence (cumulative), then sense-reversing grid barrier
__device__ __forceinline__ void grid_barrier() {
    __threadfence();
    __syncthreads();
    if (threadIdx.x == 0) {
        unsigned gen = *((volatile unsigned*)&d_bar_gen);
        unsigned old = atomicAdd(&d_bar_count, 1u);
        if (old == NCTA - 1) {
            d_bar_count = 0;
            __threadfence();
            atomicAdd(&d_bar_gen, 1u);
        } else {
            while (*((volatile unsigned*)&d_bar_gen) == gen) { __nanosleep(64); }
        }
    }
    __syncthreads();
}

// ---------------- split kernels (fp32 -> tf32 hi/lo pair, stored as float) ----------------
__global__ void split_kernel(const float* __restrict__ src, float* __restrict__ hi,
                             float* __restrict__ lo, int n) {
    int i = blockIdx.x * blockDim.x + threadIdx.x;
    if (i < n) {
        float v = src[i];
        float h = f2tf32(v);
        hi[i] = h;
        lo[i] = f2tf32(v - h);
    }
}

// x[b][s][e] -> A[(s*B+b)][e] with tf32 split
__global__ void split_x_kernel(const float* __restrict__ x, float* __restrict__ hi,
                               float* __restrict__ lo) {
    int i = blockIdx.x * blockDim.x + threadIdx.x;
    if (i < S_ * B_ * E_) {
        int e = i % E_;
        int r = i / E_;
        int s = r / B_;
        int b = r % B_;
        float v = x[((size_t)b * S_ + s) * E_ + e];
        float h = f2tf32(v);
        hi[i] = h;
        lo[i] = f2tf32(v - h);
    }
}

// xc[b][k] = concat(h_dir0[b], h_dir1[b]) tf32 hi/lo
__global__ void build_xc_kernel(const float* __restrict__ hhi, const float* __restrict__ hlo,
                                float* __restrict__ xchi, float* __restrict__ xclo) {
    int i = blockIdx.x * blockDim.x + threadIdx.x;
    if (i < B_ * 2 * H_) {
        int k = i % (2 * H_);
        int b = i / (2 * H_);
        int d = k / H_;
        int j = k % H_;
        size_t src = (size_t)(d * B_ + b) * H_ + j;
        xchi[i] = hhi[src];
        xclo[i] = hlo[src];
    }
}

// ---------------- 3-term split-tf32 GEMM (input projections only) ----------------
template <int BM, int BN>
__global__ void __launch_bounds__(256, 1)
gemm3_tf32_kernel(const float* __restrict__ Ahi, const float* __restrict__ Alo,
                  const float* __restrict__ Whi, const float* __restrict__ Wlo,
                  float* __restrict__ C, int M, int N, int K,
                  long aBatch, long wBatch, long cBatch) {
    constexpr int BK = 16;
    constexpr int LDS = BK + 4;
    const int z = blockIdx.z;
    Ahi += (size_t)z * aBatch; Alo += (size_t)z * aBatch;
    Whi += (size_t)z * wBatch; Wlo += (size_t)z * wBatch;
    C += (size_t)z * cBatch;
    const int m0 = blockIdx.y * BM, n0 = blockIdx.x * BN;
    const int tid = threadIdx.x;

    __shared__ __align__(16) float sAh[BM][LDS];
    __shared__ __align__(16) float sAl[BM][LDS];
    __shared__ __align__(16) float sBh[BN][LDS];
    __shared__ __align__(16) float sBl[BN][LDS];

    wmma::fragment<wmma::accumulator, 16, 16, 8, float> accM0[2][2], accM1[2][2], accX[2][2];
#pragma unroll
    for (int i = 0; i < 2; i++)
#pragma unroll
        for (int j = 0; j < 2; j++) {
            wmma::fill_fragment(accM0[i][j], 0.f);
            wmma::fill_fragment(accM1[i][j], 0.f);
            wmma::fill_fragment(accX[i][j], 0.f);
        }

    const int wid = tid >> 5;
    const int wm = wid >> 2;
    const int wn = wid & 3;
    const int Khalf = K >> 1;

    for (int k0 = 0; k0 < K; k0 += BK) {
#pragma unroll
        for (int i = tid; i < BM * (BK / 4); i += 256) {
            int r = i / (BK / 4), q = i % (BK / 4);
            size_t g = (size_t)(m0 + r) * K + k0 + q * 4;
            *(float4*)&sAh[r][q * 4] = *(const float4*)(Ahi + g);
            *(float4*)&sAl[r][q * 4] = *(const float4*)(Alo + g);
        }
#pragma unroll
        for (int i = tid; i < BN * (BK / 4); i += 256) {
            int r = i / (BK / 4), q = i % (BK / 4);
            size_t g = (size_t)(n0 + r) * K + k0 + q * 4;
            *(float4*)&sBh[r][q * 4] = *(const float4*)(Whi + g);
            *(float4*)&sBl[r][q * 4] = *(const float4*)(Wlo + g);
        }
        __syncthreads();
        const bool firstHalf = (k0 < Khalf);
#pragma unroll
        for (int kk = 0; kk < BK; kk += 8) {
            wmma::fragment<wmma::matrix_a, 16, 16, 8, wmma::precision::tf32, wmma::row_major> ah[2], al[2];
            wmma::fragment<wmma::matrix_b, 16, 16, 8, wmma::precision::tf32, wmma::col_major> bh[2], bl[2];
#pragma unroll
            for (int i = 0; i < 2; i++) {
                wmma::load_matrix_sync(ah[i], &sAh[wm * 32 + i * 16][kk], LDS);
                wmma::load_matrix_sync(al[i], &sAl[wm * 32 + i * 16][kk], LDS);
                wmma::load_matrix_sync(bh[i], &sBh[wn * 32 + i * 16][kk], LDS);
                wmma::load_matrix_sync(bl[i], &sBl[wn * 32 + i * 16][kk], LDS);
            }
            if (firstHalf) {
#pragma unroll
                for (int i = 0; i < 2; i++)
#pragma unroll
                    for (int j = 0; j < 2; j++)
                        wmma::mma_sync(accM0[i][j], ah[i], bh[j], accM0[i][j]);
            } else {
#pragma unroll
                for (int i = 0; i < 2; i++)
#pragma unroll
                    for (int j = 0; j < 2; j++)
                        wmma::mma_sync(accM1[i][j], ah[i], bh[j], accM1[i][j]);
            }
#pragma unroll
            for (int i = 0; i < 2; i++)
#pragma unroll
                for (int j = 0; j < 2; j++) {
                    wmma::mma_sync(accX[i][j], ah[i], bl[j], accX[i][j]);
                    wmma::mma_sync(accX[i][j], al[i], bh[j], accX[i][j]);
                }
        }
        __syncthreads();
    }
#pragma unroll
    for (int i = 0; i < 2; i++)
#pragma unroll
        for (int j = 0; j < 2; j++) {
#pragma unroll
            for (int e = 0; e < accM0[i][j].num_elements; e++)
                accM0[i][j].x[e] = (float)(((double)accM0[i][j].x[e] + (double)accM1[i][j].x[e])
                                           + (double)accX[i][j].x[e]);
            wmma::store_matrix_sync(&C[(size_t)(m0 + wm * 32 + i * 16) * N + n0 + wn * 32 + j * 16],
                                    accM0[i][j], N, wmma::mem_row_major);
        }
}

// ---------------- row LayerNorm (in-place, width 2048, two-pass fp64 stats) ----------------
__global__ void ln_rows_kernel(float* __restrict__ data, const float* __restrict__ gamma,
                               const float* __restrict__ beta, int rowsPerDir) {
    __shared__ double red[8];
    const int width = G_;
    long row = blockIdx.x;
    int d = (int)(row / rowsPerDir);
    float* p = data + row * (long)width;
    const int tid = threadIdx.x;
    float v[8];
    double s = 0.0;
#pragma unroll
    for (int q = 0; q < 8; q++) {
        v[q] = p[tid + q * 256];
        s += (double)v[q];
    }
    s = block_reduce_d(s, red);
    double mu = s / width;
    double sq = 0.0;
#pragma unroll
    for (int q = 0; q < 8; q++) {
        double dv = (double)v[q] - mu;
        sq += dv * dv;
    }
    sq = block_reduce_d(sq, red);
    double rstd = rsqrt(sq / width + 1e-5);
    const float* g = gamma + (size_t)d * width;
    const float* be = beta + (size_t)d * width;
#pragma unroll
    for (int q = 0; q < 8; q++) {
        int j = tid + q * 256;
        p[j] = (float)(((double)v[q] - mu) * rstd * (double)g[j] + (double)be[j]);
    }
}

// ================= persistent scan kernel: full 48-step bidirectional layer ==============
// 128 CTAs x 256 threads, 1 CTA/SM (150KB smem) -> all resident -> grid barrier safe.
// GEMM role: CTA (d = cta/64, n0 = (cta%64)*32) computes Z[d][0:64][n0:n0+32].
// Cell role: CTA r handles row r = d*64+b; c state lives in registers across all steps.
__global__ void __launch_bounds__(256, 1)
scan_kernel(const float* __restrict__ Whh_hi, const float* __restrict__ Whh_lo,
            const float* __restrict__ gih, long gihTime, long gihDir,
            const float* __restrict__ g_hh, const float* __restrict__ b_hh,
            const float* __restrict__ g_ho, const float* __restrict__ b_ho,
            float* __restrict__ Z, float* __restrict__ hhi, float* __restrict__ hlo,
            int writeOut, float* __restrict__ out) {
    extern __shared__ float sm[];
    float* sWh = sm;                       // [32][512]
    float* sWl = sm + 32 * 512;            // [32][512]
    float* sAh = sm + 2 * 32 * 512;        // [64][36]
    float* sAl = sAh + 64 * 36;            // [64][36]
    __shared__ double red[8];

    const int tid = threadIdx.x;
    const int cta = blockIdx.x;
    const int d = cta >> 6;                // gemm dir
    const int n0 = (cta & 63) * 32;        // gemm column block
    const int wid = tid >> 5;
    const int wm = wid >> 1;               // 0..3 (16-row slice)
    const int wn = wid & 1;                // 0..1 (16-col slice)

    // cache this CTA's weight slice (rows n0..n0+31 of W[d], all K) in smem
    {
        const float4* wh = (const float4*)(Whh_hi + ((size_t)d * G_ + n0) * H_);
        const float4* wl = (const float4*)(Whh_lo + ((size_t)d * G_ + n0) * H_);
        float4* dh = (float4*)sWh;
        float4* dl = (float4*)sWl;
        for (int i = tid; i < 32 * (H_ / 4); i += 256) {
            dh[i] = wh[i];
            dl[i] = wl[i];
        }
    }
    // zero my h row (row r = cta)
    {
        float* ph = hhi + (size_t)cta * H_;
        float* pl = hlo + (size_t)cta * H_;
        for (int i = tid; i < H_; i += 256) { ph[i] = 0.f; pl[i] = 0.f; }
    }
    double c_reg0 = 0.0, c_reg1 = 0.0;     // persistent cell state (2 per thread)
    grid_barrier();

    for (int t = 0; t < S_; t++) {
        // ======== GEMM phase: Z[d][m][n0+n] = sum_k h[d][m][k] * W[d][n0+n][k] ========
        wmma::fragment<wmma::accumulator, 16, 16, 8, float> accM0, accM1, accX;
        wmma::fill_fragment(accM0, 0.f);
        wmma::fill_fragment(accM1, 0.f);
        wmma::fill_fragment(accX, 0.f);

        for (int k0 = 0; k0 < H_; k0 += 32) {
            // load A tile [64 x 32] hi+lo via L2 (cross-CTA data)
#pragma unroll
            for (int i = 0; i < 2; i++) {
                int idx = tid + i * 256;
                int r = idx >> 3, q = idx & 7;
                size_t gaddr = (size_t)(d * B_ + r) * H_ + k0 + q * 4;
                float4 vh = __ldcg((const float4*)(hhi + gaddr));
                float4 vl = __ldcg((const float4*)(hlo + gaddr));
                *(float4*)&sAh[r * 36 + q * 4] = vh;
                *(float4*)&sAl[r * 36 + q * 4] = vl;
            }
            __syncthreads();
            const bool firstHalf = (k0 < (H_ / 2));
#pragma unroll
            for (int kk = 0; kk < 32; kk += 8) {
                wmma::fragment<wmma::matrix_a, 16, 16, 8, wmma::precision::tf32, wmma::row_major> ah, al;
                wmma::fragment<wmma::matrix_b, 16, 16, 8, wmma::precision::tf32, wmma::col_major> bh, bl;
                wmma::load_matrix_sync(ah, &sAh[(wm * 16) * 36 + kk], 36);
                wmma::load_matrix_sync(al, &sAl[(wm * 16) * 36 + kk], 36);
                wmma::load_matrix_sync(bh, &sWh[(wn * 16) * H_ + k0 + kk], H_);
                wmma::load_matrix_sync(bl, &sWl[(wn * 16) * H_ + k0 + kk], H_);
                if (firstHalf) wmma::mma_sync(accM0, ah, bh, accM0);
                else           wmma::mma_sync(accM1, ah, bh, accM1);
                wmma::mma_sync(accX, ah, bl, accX);
                wmma::mma_sync(accX, al, bh, accX);
            }
            __syncthreads();
        }
#pragma unroll
        for (int e = 0; e < accM0.num_elements; e++)
            accM0.x[e] = (float)(((double)accM0.x[e] + (double)accM1.x[e]) + (double)accX.x[e]);
        wmma::store_matrix_sync(Z + (size_t)(d * B_ + wm * 16) * G_ + n0 + wn * 16,
                                accM0, G_, wmma::mem_row_major);

        grid_barrier();

        // ======== cell phase: this CTA handles row cta = (cd, cb) ========
        {
            const int cd = d, cb = cta & 63;
            const float* z = Z + (size_t)cta * G_;
            const int tt = (cd == 0) ? t : (S_ - 1 - t);
            const float* gi = gih + (size_t)cd * gihDir + (size_t)tt * gihTime + (size_t)cb * G_;

            float zr[8];
            double s = 0.0;
#pragma unroll
            for (int q = 0; q < 8; q++) {
                zr[q] = __ldcg(z + tid + q * 256);
                s += (double)zr[q];
            }
            s = block_reduce_d(s, red);
            double mu = s / G_;
            double sq = 0.0;
#pragma unroll
            for (int q = 0; q < 8; q++) {
                double dv = (double)zr[q] - mu;
                sq += dv * dv;
            }
            sq = block_reduce_d(sq, red);
            double rstd = rsqrt(sq / G_ + 1e-5);

            const float* ghh = g_hh + (size_t)cd * G_;
            const float* bhh = b_hh + (size_t)cd * G_;
            double cn_st[2], o_st[2];
            double s2 = 0.0;
#pragma unroll
            for (int cnt = 0; cnt < 2; cnt++) {
                int j = tid + cnt * 256;
                double ai = (double)gi[j]          + ((double)zr[cnt]     - mu) * rstd * (double)ghh[j]          + (double)bhh[j];
                double af = (double)gi[j + H_]     + ((double)zr[cnt + 2] - mu) * rstd * (double)ghh[j + H_]     + (double)bhh[j + H_];
                double ao = (double)gi[j + 2 * H_] + ((double)zr[cnt + 4] - mu) * rstd * (double)ghh[j + 2 * H_] + (double)bhh[j + 2 * H_];
                double ag = (double)gi[j + 3 * H_] + ((double)zr[cnt + 6] - mu) * rstd * (double)ghh[j + 3 * H_] + (double)bhh[j + 3 * H_];
                double ig = (double)sigmoidf_((float)ai);
                double fg = (double)sigmoidf_((float)af);
                double og = (double)sigmoidf_((float)ao);
                double gg = (double)tanhf((float)ag);
                double cold = (cnt == 0) ? c_reg0 : c_reg1;
                double cn = fg * cold + ig * gg;
                if (cnt == 0) c_reg0 = cn; else c_reg1 = cn;
                cn_st[cnt] = cn;
                o_st[cnt] = og;
                s2 += cn;
            }
            s2 = block_reduce_d(s2, red);
            double muc = s2 / H_;
            double sq2 = 0.0;
#pragma unroll
            for (int cnt = 0; cnt < 2; cnt++) {
                double dv = cn_st[cnt] - muc;
                sq2 += dv * dv;
            }
            sq2 = block_reduce_d(sq2, red);
            double rstdc = rsqrt(sq2 / H_ + 1e-5);

            const float* gho = g_ho + (size_t)cd * H_;
            const float* bho = b_ho + (size_t)cd * H_;
#pragma unroll
            for (int cnt = 0; cnt < 2; cnt++) {
                int j = tid + cnt * 256;
                double lnc = (cn_st[cnt] - muc) * rstdc * (double)gho[j] + (double)bho[j];
                double hn = o_st[cnt] * (double)tanhf((float)lnc);
                size_t hi_ = (size_t)cta * H_ + j;
                float hv = (float)hn;
                float hb = f2tf32(hv);
                hhi[hi_] = hb;
                hlo[hi_] = f2tf32(hv - hb);
                if (writeOut && t == S_ - 1)
                    out[(size_t)cb * (2 * H_) + (size_t)cd * H_ + j] = (float)hn;
            }
        }
        grid_barrier();
    }
}

// ---------------- host orchestration ----------------
extern "C" void kernel_launch(void* const* d_in, const int* in_sizes, int n_in,
                              void* d_out, int out_size) {
    const float* x = (const float*)d_in[0];
    // d_in[1] = text_length (unused)
    const float* w_ih0 = (const float*)d_in[2];
    const float* w_hh0 = (const float*)d_in[3];
    const float* ln_ih0_g = (const float*)d_in[4];
    const float* ln_ih0_b = (const float*)d_in[5];
    const float* ln_hh0_g = (const float*)d_in[6];
    const float* ln_hh0_b = (const float*)d_in[7];
    const float* ln_ho0_g = (const float*)d_in[8];
    const float* ln_ho0_b = (const float*)d_in[9];
    const float* w_ih1 = (const float*)d_in[10];
    const float* w_hh1 = (const float*)d_in[11];
    const float* ln_ih1_g = (const float*)d_in[12];
    const float* ln_ih1_b = (const float*)d_in[13];
    const float* ln_hh1_g = (const float*)d_in[14];
    const float* ln_hh1_b = (const float*)d_in[15];
    const float* ln_ho1_g = (const float*)d_in[16];
    const float* ln_ho1_b = (const float*)d_in[17];
    float* out = (float*)d_out;

    float *G0, *G1, *Z;
    float *hhi, *hlo, *A0hi, *A0lo, *Wih0hi, *Wih0lo, *Whh0hi, *Whh0lo;
    float *Wih1hi, *Wih1lo, *Whh1hi, *Whh1lo, *XChi, *XClo;
    cudaGetSymbolAddress((void**)&G0, d_G0);
    cudaGetSymbolAddress((void**)&G1, d_G1);
    cudaGetSymbolAddress((void**)&Z, d_Zb);
    cudaGetSymbolAddress((void**)&hhi, d_hhi);
    cudaGetSymbolAddress((void**)&hlo, d_hlo);
    cudaGetSymbolAddress((void**)&A0hi, d_A0hi);
    cudaGetSymbolAddress((void**)&A0lo, d_A0lo);
    cudaGetSymbolAddress((void**)&Wih0hi, d_Wih0hi);
    cudaGetSymbolAddress((void**)&Wih0lo, d_Wih0lo);
    cudaGetSymbolAddress((void**)&Whh0hi, d_Whh0hi);
    cudaGetSymbolAddress((void**)&Whh0lo, d_Whh0lo);
    cudaGetSymbolAddress((void**)&Wih1hi, d_Wih1hi);
    cudaGetSymbolAddress((void**)&Wih1lo, d_Wih1lo);
    cudaGetSymbolAddress((void**)&Whh1hi, d_Whh1hi);
    cudaGetSymbolAddress((void**)&Whh1lo, d_Whh1lo);
    cudaGetSymbolAddress((void**)&XChi, d_XChi);
    cudaGetSymbolAddress((void**)&XClo, d_XClo);

    const int SCAN_SMEM = (2 * 32 * 512 + 2 * 64 * 36) * 4;  // 149504 B
    static int attr_set = 0;
    if (!attr_set) {
        cudaFuncSetAttribute(scan_kernel, cudaFuncAttributeMaxDynamicSharedMemorySize, SCAN_SMEM);
        attr_set = 1;
    }

    int n;
    n = S_ * B_ * E_;
    split_x_kernel<<<(n + 255) / 256, 256>>>(x, A0hi, A0lo);
    n = 2 * G_ * E_;
    split_kernel<<<(n + 255) / 256, 256>>>(w_ih0, Wih0hi, Wih0lo, n);
    n = 2 * G_ * H_;
    split_kernel<<<(n + 255) / 256, 256>>>(w_hh0, Whh0hi, Whh0lo, n);
    n = 2 * G_ * 2 * H_;
    split_kernel<<<(n + 255) / 256, 256>>>(w_ih1, Wih1hi, Wih1lo, n);
    n = 2 * G_ * H_;
    split_kernel<<<(n + 255) / 256, 256>>>(w_hh1, Whh1hi, Whh1lo, n);

    // layer-0 input projection: [3072,512] x [2048,512]^T per dir
    {
        dim3 grid(G_ / 128, (S_ * B_) / 64, 2);
        gemm3_tf32_kernel<64, 128><<<grid, 256>>>(A0hi, A0lo, Wih0hi, Wih0lo, G0,
                                                  S_ * B_, G_, E_,
                                                  0L, (long)G_ * E_, (long)S_ * B_ * G_);
    }
    ln_rows_kernel<<<2 * S_ * B_, 256>>>(G0, ln_ih0_g, ln_ih0_b, S_ * B_);

    // ---- layer 0 scan (persistent) ----
    scan_kernel<<<NCTA, 256, SCAN_SMEM>>>(Whh0hi, Whh0lo,
                                          G0, (long)B_ * G_, (long)S_ * B_ * G_,
                                          ln_hh0_g, ln_hh0_b, ln_ho0_g, ln_ho0_b,
                                          Z, hhi, hlo, 0, out);

    // ---- layer 1 input (constant over time due to aliasing bug) ----
    build_xc_kernel<<<(B_ * 2 * H_ + 255) / 256, 256>>>(hhi, hlo, XChi, XClo);
    {
        dim3 grid(G_ / 128, 1, 2);
        gemm3_tf32_kernel<64, 128><<<grid, 256>>>(XChi, XClo, Wih1hi, Wih1lo, G1,
                                                  B_, G_, 2 * H_,
                                                  0L, (long)G_ * 2 * H_, (long)B_ * G_);
    }
    ln_rows_kernel<<<2 * B_, 256>>>(G1, ln_ih1_g, ln_ih1_b, B_);

    // ---- layer 1 scan (persistent) ----
    scan_kernel<<<NCTA, 256, SCAN_SMEM>>>(Whh1hi, Whh1lo,
                                          G1, 0L, (long)B_ * G_,
                                          ln_hh1_g, ln_hh1_b, ln_ho1_g, ln_ho1_b,
                                          Z, hhi, hlo, 1, out);
}

// round 10
// speedup vs baseline: 2.9509x; 1.9435x over previous
#include <cuda_runtime.h>
#include <cuda_bf16.h>
#include <mma.h>

using namespace nvcuda;

#define B_ 64
#define S_ 48
#define E_ 512
#define H_ 512
#define G_ 2048  /* 4H */
#define NCTA 128

// ---------------- scratch (static device memory; no allocations) ----------------
__device__ __align__(16) float d_G0[2 * S_ * B_ * G_];   // LN(x@Wih0^T), both dirs
__device__ __align__(16) float d_G1[2 * B_ * G_];        // LN(xc@Wih1^T)
__device__ __align__(16) float d_Zb[2 * B_ * G_];        // per-step h@Whh^T
// tf32 hi/lo pairs stored as float
__device__ __align__(16) float d_hhi[2 * B_ * H_], d_hlo[2 * B_ * H_];
__device__ __align__(16) float d_A0hi[S_ * B_ * E_], d_A0lo[S_ * B_ * E_];
__device__ __align__(16) float d_Wih0hi[2 * G_ * E_], d_Wih0lo[2 * G_ * E_];
__device__ __align__(16) float d_Whh0hi[2 * G_ * H_], d_Whh0lo[2 * G_ * H_];
__device__ __align__(16) float d_Wih1hi[2 * G_ * 2 * H_], d_Wih1lo[2 * G_ * 2 * H_];
__device__ __align__(16) float d_Whh1hi[2 * G_ * H_], d_Whh1lo[2 * G_ * H_];
__device__ __align__(16) float d_XChi[B_ * 2 * H_], d_XClo[B_ * 2 * H_];

// grid-barrier state
__device__ unsigned d_bar_count = 0;
__device__ unsigned d_bar_gen = 0;

// ---------------- helpers ----------------
__device__ __forceinline__ float f2tf32(float x) {
    unsigned r;
    asm("cvt.rna.tf32.f32 %0, %1;" : "=r"(r) : "f"(x));
    return __uint_as_float(r);
}

__device__ __forceinline__ double block_reduce_d(double a, double* buf) {
    __syncthreads();
    for (int o = 16; o > 0; o >>= 1)
        a += __shfl_down_sync(0xffffffffu, a, o);
    int w = threadIdx.x >> 5;
    if ((threadIdx.x & 31) == 0) buf[w] = a;
    __syncthreads();
    int nw = (blockDim.x + 31) >> 5;
    double s = 0.0;
    for (int i = 0; i < nw; i++) s += buf[i];
    return s;
}

__device__ __forceinline__ float sigmoidf_(float x) { return 1.f / (1.f + expf(-x)); }

// CG-style grid barrier: intra-CTA sync, then thread0 release-fence + atomic + spin.
__device__ __forceinline__ void grid_barrier() {
    __syncthreads();
    if (threadIdx.x == 0) {
        __threadfence();
        unsigned gen = *((volatile unsigned*)&d_bar_gen);
        unsigned old = atomicAdd(&d_bar_count, 1u);
        if (old == NCTA - 1) {
            d_bar_count = 0;
            __threadfence();
            atomicAdd(&d_bar_gen, 1u);
        } else {
            while (*((volatile unsigned*)&d_bar_gen) == gen) { __nanosleep(32); }
        }
    }
    __syncthreads();
}

// ---------------- split kernels (fp32 -> tf32 hi/lo, float4-vectorized) ----------------
__device__ __forceinline__ void split4(float4 v, float4& h, float4& l) {
    h.x = f2tf32(v.x); l.x = f2tf32(v.x - h.x);
    h.y = f2tf32(v.y); l.y = f2tf32(v.y - h.y);
    h.z = f2tf32(v.z); l.z = f2tf32(v.z - h.z);
    h.w = f2tf32(v.w); l.w = f2tf32(v.w - h.w);
}

// fused split of all 4 weight tensors (sizes in float4 units)
__global__ void split_weights_kernel(const float* __restrict__ s0, float* __restrict__ h0, float* __restrict__ l0, int n0,
                                     const float* __restrict__ s1, float* __restrict__ h1, float* __restrict__ l1, int n1,
                                     const float* __restrict__ s2, float* __restrict__ h2, float* __restrict__ l2, int n2,
                                     const float* __restrict__ s3, float* __restrict__ h3, float* __restrict__ l3, int n3) {
    int i = blockIdx.x * blockDim.x + threadIdx.x;  // float4 index
    const float* s; float* h; float* l;
    if (i < n0) { s = s0; h = h0; l = l0; }
    else if ((i -= n0) < n1) { s = s1; h = h1; l = l1; }
    else if ((i -= n1) < n2) { s = s2; h = h2; l = l2; }
    else if ((i -= n2) < n3) { s = s3; h = h3; l = l3; }
    else return;
    float4 v = ((const float4*)s)[i], hv, lv;
    split4(v, hv, lv);
    ((float4*)h)[i] = hv;
    ((float4*)l)[i] = lv;
}

// x[b][s][e] -> A[(s*B+b)][e] with tf32 split (float4 over e)
__global__ void split_x_kernel(const float* __restrict__ x, float* __restrict__ hi,
                               float* __restrict__ lo) {
    int i = blockIdx.x * blockDim.x + threadIdx.x;  // float4 index
    if (i < S_ * B_ * (E_ / 4)) {
        int e4 = i % (E_ / 4);
        int r = i / (E_ / 4);
        int s = r / B_;
        int b = r % B_;
        float4 v = *(const float4*)(x + ((size_t)b * S_ + s) * E_ + e4 * 4);
        float4 hv, lv;
        split4(v, hv, lv);
        ((float4*)hi)[i] = hv;
        ((float4*)lo)[i] = lv;
    }
}

// xc[b][k] = concat(h_dir0[b], h_dir1[b]) tf32 hi/lo
__global__ void build_xc_kernel(const float* __restrict__ hhi, const float* __restrict__ hlo,
                                float* __restrict__ xchi, float* __restrict__ xclo) {
    int i = blockIdx.x * blockDim.x + threadIdx.x;
    if (i < B_ * 2 * H_) {
        int k = i % (2 * H_);
        int b = i / (2 * H_);
        int d = k / H_;
        int j = k % H_;
        size_t src = (size_t)(d * B_ + b) * H_ + j;
        xchi[i] = hhi[src];
        xclo[i] = hlo[src];
    }
}

// ---------------- 3-term split-tf32 GEMM (input projections only) ----------------
template <int BM, int BN>
__global__ void __launch_bounds__(256, 1)
gemm3_tf32_kernel(const float* __restrict__ Ahi, const float* __restrict__ Alo,
                  const float* __restrict__ Whi, const float* __restrict__ Wlo,
                  float* __restrict__ C, int M, int N, int K,
                  long aBatch, long wBatch, long cBatch) {
    constexpr int BK = 16;
    constexpr int LDS = BK + 4;
    const int z = blockIdx.z;
    Ahi += (size_t)z * aBatch; Alo += (size_t)z * aBatch;
    Whi += (size_t)z * wBatch; Wlo += (size_t)z * wBatch;
    C += (size_t)z * cBatch;
    const int m0 = blockIdx.y * BM, n0 = blockIdx.x * BN;
    const int tid = threadIdx.x;

    __shared__ __align__(16) float sAh[BM][LDS];
    __shared__ __align__(16) float sAl[BM][LDS];
    __shared__ __align__(16) float sBh[BN][LDS];
    __shared__ __align__(16) float sBl[BN][LDS];

    wmma::fragment<wmma::accumulator, 16, 16, 8, float> accM0[2][2], accM1[2][2], accX[2][2];
#pragma unroll
    for (int i = 0; i < 2; i++)
#pragma unroll
        for (int j = 0; j < 2; j++) {
            wmma::fill_fragment(accM0[i][j], 0.f);
            wmma::fill_fragment(accM1[i][j], 0.f);
            wmma::fill_fragment(accX[i][j], 0.f);
        }

    const int wid = tid >> 5;
    const int wm = wid >> 2;
    const int wn = wid & 3;
    const int Khalf = K >> 1;

    for (int k0 = 0; k0 < K; k0 += BK) {
#pragma unroll
        for (int i = tid; i < BM * (BK / 4); i += 256) {
            int r = i / (BK / 4), q = i % (BK / 4);
            size_t g = (size_t)(m0 + r) * K + k0 + q * 4;
            *(float4*)&sAh[r][q * 4] = *(const float4*)(Ahi + g);
            *(float4*)&sAl[r][q * 4] = *(const float4*)(Alo + g);
        }
#pragma unroll
        for (int i = tid; i < BN * (BK / 4); i += 256) {
            int r = i / (BK / 4), q = i % (BK / 4);
            size_t g = (size_t)(n0 + r) * K + k0 + q * 4;
            *(float4*)&sBh[r][q * 4] = *(const float4*)(Whi + g);
            *(float4*)&sBl[r][q * 4] = *(const float4*)(Wlo + g);
        }
        __syncthreads();
        const bool firstHalf = (k0 < Khalf);
#pragma unroll
        for (int kk = 0; kk < BK; kk += 8) {
            wmma::fragment<wmma::matrix_a, 16, 16, 8, wmma::precision::tf32, wmma::row_major> ah[2], al[2];
            wmma::fragment<wmma::matrix_b, 16, 16, 8, wmma::precision::tf32, wmma::col_major> bh[2], bl[2];
#pragma unroll
            for (int i = 0; i < 2; i++) {
                wmma::load_matrix_sync(ah[i], &sAh[wm * 32 + i * 16][kk], LDS);
                wmma::load_matrix_sync(al[i], &sAl[wm * 32 + i * 16][kk], LDS);
                wmma::load_matrix_sync(bh[i], &sBh[wn * 32 + i * 16][kk], LDS);
                wmma::load_matrix_sync(bl[i], &sBl[wn * 32 + i * 16][kk], LDS);
            }
            if (firstHalf) {
#pragma unroll
                for (int i = 0; i < 2; i++)
#pragma unroll
                    for (int j = 0; j < 2; j++)
                        wmma::mma_sync(accM0[i][j], ah[i], bh[j], accM0[i][j]);
            } else {
#pragma unroll
                for (int i = 0; i < 2; i++)
#pragma unroll
                    for (int j = 0; j < 2; j++)
                        wmma::mma_sync(accM1[i][j], ah[i], bh[j], accM1[i][j]);
            }
#pragma unroll
            for (int i = 0; i < 2; i++)
#pragma unroll
                for (int j = 0; j < 2; j++) {
                    wmma::mma_sync(accX[i][j], ah[i], bl[j], accX[i][j]);
                    wmma::mma_sync(accX[i][j], al[i], bh[j], accX[i][j]);
                }
        }
        __syncthreads();
    }
#pragma unroll
    for (int i = 0; i < 2; i++)
#pragma unroll
        for (int j = 0; j < 2; j++) {
#pragma unroll
            for (int e = 0; e < accM0[i][j].num_elements; e++)
                accM0[i][j].x[e] = (float)(((double)accM0[i][j].x[e] + (double)accM1[i][j].x[e])
                                           + (double)accX[i][j].x[e]);
            wmma::store_matrix_sync(&C[(size_t)(m0 + wm * 32 + i * 16) * N + n0 + wn * 32 + j * 16],
                                    accM0[i][j], N, wmma::mem_row_major);
        }
}

// ---------------- row LayerNorm (in-place, width 2048, two-pass fp64 stats) ----------------
__global__ void ln_rows_kernel(float* __restrict__ data, const float* __restrict__ gamma,
                               const float* __restrict__ beta, int rowsPerDir) {
    __shared__ double red[8];
    const int width = G_;
    long row = blockIdx.x;
    int d = (int)(row / rowsPerDir);
    float* p = data + row * (long)width;
    const int tid = threadIdx.x;
    float v[8];
    double s = 0.0;
#pragma unroll
    for (int q = 0; q < 8; q++) {
        v[q] = p[tid + q * 256];
        s += (double)v[q];
    }
    s = block_reduce_d(s, red);
    double mu = s / width;
    double sq = 0.0;
#pragma unroll
    for (int q = 0; q < 8; q++) {
        double dv = (double)v[q] - mu;
        sq += dv * dv;
    }
    sq = block_reduce_d(sq, red);
    double rstd = rsqrt(sq / width + 1e-5);
    const float* g = gamma + (size_t)d * width;
    const float* be = beta + (size_t)d * width;
#pragma unroll
    for (int q = 0; q < 8; q++) {
        int j = tid + q * 256;
        p[j] = (float)(((double)v[q] - mu) * rstd * (double)g[j] + (double)be[j]);
    }
}

// ================= persistent scan kernel =================
// 128 CTAs x 256 threads, 1 CTA/SM.
// SMEM (dynamic, 192512B):
//   sWh,sWl : 16 k-blocks of [32 n][33 k]   (conflict-free fragment loads)
//   sA      : double-buffered A tiles [2][hi/lo][64][36]
//   sGhh,sBhh [2048], sGho,sBho [512]       (this dir's LN params)
__global__ void __launch_bounds__(256, 1)
scan_kernel(const float* __restrict__ Whh_hi, const float* __restrict__ Whh_lo,
            const float* __restrict__ gih, long gihTime, long gihDir,
            const float* __restrict__ g_hh, const float* __restrict__ b_hh,
            const float* __restrict__ g_ho, const float* __restrict__ b_ho,
            float* __restrict__ Z, float* __restrict__ hhi, float* __restrict__ hlo,
            int writeOut, float* __restrict__ out) {
    extern __shared__ float sm[];
    float* sWh = sm;                          // 16*32*33 = 16896
    float* sWl = sWh + 16896;                 // 16896
    float* sA = sWl + 16896;                  // 2 buf * 2 (hi,lo) * 2304
    float* sGhh = sA + 9216;                  // 2048
    float* sBhh = sGhh + 2048;                // 2048
    float* sGho = sBhh + 2048;                // 512
    float* sBho = sGho + 512;                 // 512
    __shared__ double red[8];

    const int tid = threadIdx.x;
    const int cta = blockIdx.x;
    const int d = cta >> 6;                   // direction (gemm + cell)
    const int n0 = (cta & 63) * 32;           // gemm column block
    const int cb = cta & 63;                  // cell batch row
    const int wid = tid >> 5;
    const int wm = wid >> 1;                  // 0..3 (16-row slice of m)
    const int wn = wid & 1;                   // 0..1 (16-col slice of n)

    // ---- one-time fills ----
    // W slice rows n0..n0+31 into blocked [kb][r][33]
    {
        const float* wh = Whh_hi + ((size_t)d * G_ + n0) * H_;
        const float* wl = Whh_lo + ((size_t)d * G_ + n0) * H_;
        for (int i = tid; i < 32 * H_; i += 256) {
            int r = i >> 9, k = i & 511;
            int kb = k >> 5, kk = k & 31;
            int off = kb * (32 * 33) + r * 33 + kk;
            sWh[off] = __ldg(wh + (size_t)r * H_ + k);
            sWl[off] = __ldg(wl + (size_t)r * H_ + k);
        }
    }
    // LN params for this dir
    for (int i = tid; i < G_; i += 256) {
        sGhh[i] = __ldg(g_hh + (size_t)d * G_ + i);
        sBhh[i] = __ldg(b_hh + (size_t)d * G_ + i);
    }
    for (int i = tid; i < H_; i += 256) {
        sGho[i] = __ldg(g_ho + (size_t)d * H_ + i);
        sBho[i] = __ldg(b_ho + (size_t)d * H_ + i);
    }
    // zero my h row
    {
        float* ph = hhi + (size_t)cta * H_;
        float* pl = hlo + (size_t)cta * H_;
        for (int i = tid; i < H_; i += 256) { ph[i] = 0.f; pl[i] = 0.f; }
    }
    double c_reg0 = 0.0, c_reg1 = 0.0;
    grid_barrier();

    // A staging indices (per thread: 2 float4 per matrix)
    const int r0 = tid >> 3, q0 = (tid & 7) * 4;            // idx = tid
    const int r1 = (tid + 256) >> 3, q1 = q0;               // idx = tid+256 (same q)

    for (int t = 0; t < S_; t++) {
        // prefetch gi for cell phase (registers; consumed after barrier)
        const int tt = (d == 0) ? t : (S_ - 1 - t);
        const float* gi = gih + (size_t)d * gihDir + (size_t)tt * gihTime + (size_t)cb * G_;
        float gir[8];
#pragma unroll
        for (int q = 0; q < 8; q++) gir[q] = __ldg(gi + tid + q * 256);

        // ======== GEMM phase ========
        wmma::fragment<wmma::accumulator, 16, 16, 8, float> accM0, accM1, accX;
        wmma::fill_fragment(accM0, 0.f);
        wmma::fill_fragment(accM1, 0.f);
        wmma::fill_fragment(accX, 0.f);

        // prefetch kb=0
        float4 rh0 = __ldcg((const float4*)(hhi + (size_t)(d * B_ + r0) * H_ + q0));
        float4 rh1 = __ldcg((const float4*)(hhi + (size_t)(d * B_ + r1) * H_ + q1));
        float4 rl0 = __ldcg((const float4*)(hlo + (size_t)(d * B_ + r0) * H_ + q0));
        float4 rl1 = __ldcg((const float4*)(hlo + (size_t)(d * B_ + r1) * H_ + q1));

#pragma unroll 4
        for (int kb = 0; kb < 16; kb++) {
            float* bAh = sA + (kb & 1) * 4608;
            float* bAl = bAh + 2304;
            *(float4*)&bAh[r0 * 36 + q0] = rh0;
            *(float4*)&bAh[r1 * 36 + q1] = rh1;
            *(float4*)&bAl[r0 * 36 + q0] = rl0;
            *(float4*)&bAl[r1 * 36 + q1] = rl1;
            __syncthreads();
            if (kb < 15) {
                int k0n = (kb + 1) * 32;
                rh0 = __ldcg((const float4*)(hhi + (size_t)(d * B_ + r0) * H_ + k0n + q0));
                rh1 = __ldcg((const float4*)(hhi + (size_t)(d * B_ + r1) * H_ + k0n + q1));
                rl0 = __ldcg((const float4*)(hlo + (size_t)(d * B_ + r0) * H_ + k0n + q0));
                rl1 = __ldcg((const float4*)(hlo + (size_t)(d * B_ + r1) * H_ + k0n + q1));
            }
            const float* bWh = sWh + kb * (32 * 33) + (wn * 16) * 33;
            const float* bWl = sWl + kb * (32 * 33) + (wn * 16) * 33;
#pragma unroll
            for (int kk = 0; kk < 32; kk += 8) {
                wmma::fragment<wmma::matrix_a, 16, 16, 8, wmma::precision::tf32, wmma::row_major> ah, al;
                wmma::fragment<wmma::matrix_b, 16, 16, 8, wmma::precision::tf32, wmma::col_major> bh, bl;
                wmma::load_matrix_sync(ah, &bAh[(wm * 16) * 36 + kk], 36);
                wmma::load_matrix_sync(al, &bAl[(wm * 16) * 36 + kk], 36);
                wmma::load_matrix_sync(bh, bWh + kk, 33);
                wmma::load_matrix_sync(bl, bWl + kk, 33);
                if (kb < 8) wmma::mma_sync(accM0, ah, bh, accM0);
                else        wmma::mma_sync(accM1, ah, bh, accM1);
                wmma::mma_sync(accX, ah, bl, accX);
                wmma::mma_sync(accX, al, bh, accX);
            }
        }
#pragma unroll
        for (int e = 0; e < accM0.num_elements; e++)
            accM0.x[e] = (float)(((double)accM0.x[e] + (double)accM1.x[e]) + (double)accX.x[e]);
        wmma::store_matrix_sync(Z + (size_t)(d * B_ + wm * 16) * G_ + n0 + wn * 16,
                                accM0, G_, wmma::mem_row_major);

        grid_barrier();

        // ======== cell phase (row cta = (d, cb)) ========
        {
            const float* z = Z + (size_t)cta * G_;
            float zr[8];
            double s = 0.0;
#pragma unroll
            for (int q = 0; q < 8; q++) {
                zr[q] = __ldcg(z + tid + q * 256);
                s += (double)zr[q];
            }
            s = block_reduce_d(s, red);
            double mu = s / G_;
            double sq = 0.0;
#pragma unroll
            for (int q = 0; q < 8; q++) {
                double dv = (double)zr[q] - mu;
                sq += dv * dv;
            }
            sq = block_reduce_d(sq, red);
            double rstd = rsqrt(sq / G_ + 1e-5);

            double cn_st[2], o_st[2];
            double s2 = 0.0;
#pragma unroll
            for (int cnt = 0; cnt < 2; cnt++) {
                int j = tid + cnt * 256;
                double ai = (double)gir[cnt]     + ((double)zr[cnt]     - mu) * rstd * (double)sGhh[j]            + (double)sBhh[j];
                double af = (double)gir[cnt + 2] + ((double)zr[cnt + 2] - mu) * rstd * (double)sGhh[j + H_]       + (double)sBhh[j + H_];
                double ao = (double)gir[cnt + 4] + ((double)zr[cnt + 4] - mu) * rstd * (double)sGhh[j + 2 * H_]   + (double)sBhh[j + 2 * H_];
                double ag = (double)gir[cnt + 6] + ((double)zr[cnt + 6] - mu) * rstd * (double)sGhh[j + 3 * H_]   + (double)sBhh[j + 3 * H_];
                double ig = (double)sigmoidf_((float)ai);
                double fg = (double)sigmoidf_((float)af);
                double og = (double)sigmoidf_((float)ao);
                double gg = (double)tanhf((float)ag);
                double cold = (cnt == 0) ? c_reg0 : c_reg1;
                double cn = fg * cold + ig * gg;
                if (cnt == 0) c_reg0 = cn; else c_reg1 = cn;
                cn_st[cnt] = cn;
                o_st[cnt] = og;
                s2 += cn;
            }
            s2 = block_reduce_d(s2, red);
            double muc = s2 / H_;
            double sq2 = 0.0;
#pragma unroll
            for (int cnt = 0; cnt < 2; cnt++) {
                double dv = cn_st[cnt] - muc;
                sq2 += dv * dv;
            }
            sq2 = block_reduce_d(sq2, red);
            double rstdc = rsqrt(sq2 / H_ + 1e-5);

#pragma unroll
            for (int cnt = 0; cnt < 2; cnt++) {
                int j = tid + cnt * 256;
                double lnc = (cn_st[cnt] - muc) * rstdc * (double)sGho[j] + (double)sBho[j];
                double hn = o_st[cnt] * (double)tanhf((float)lnc);
                size_t hi_ = (size_t)cta * H_ + j;
                float hv = (float)hn;
                float hb = f2tf32(hv);
                hhi[hi_] = hb;
                hlo[hi_] = f2tf32(hv - hb);
                if (writeOut && t == S_ - 1)
                    out[(size_t)cb * (2 * H_) + (size_t)d * H_ + j] = (float)hn;
            }
        }
        grid_barrier();
    }
}

// ---------------- host orchestration ----------------
extern "C" void kernel_launch(void* const* d_in, const int* in_sizes, int n_in,
                              void* d_out, int out_size) {
    const float* x = (const float*)d_in[0];
    // d_in[1] = text_length (unused)
    const float* w_ih0 = (const float*)d_in[2];
    const float* w_hh0 = (const float*)d_in[3];
    const float* ln_ih0_g = (const float*)d_in[4];
    const float* ln_ih0_b = (const float*)d_in[5];
    const float* ln_hh0_g = (const float*)d_in[6];
    const float* ln_hh0_b = (const float*)d_in[7];
    const float* ln_ho0_g = (const float*)d_in[8];
    const float* ln_ho0_b = (const float*)d_in[9];
    const float* w_ih1 = (const float*)d_in[10];
    const float* w_hh1 = (const float*)d_in[11];
    const float* ln_ih1_g = (const float*)d_in[12];
    const float* ln_ih1_b = (const float*)d_in[13];
    const float* ln_hh1_g = (const float*)d_in[14];
    const float* ln_hh1_b = (const float*)d_in[15];
    const float* ln_ho1_g = (const float*)d_in[16];
    const float* ln_ho1_b = (const float*)d_in[17];
    float* out = (float*)d_out;

    float *G0, *G1, *Z;
    float *hhi, *hlo, *A0hi, *A0lo, *Wih0hi, *Wih0lo, *Whh0hi, *Whh0lo;
    float *Wih1hi, *Wih1lo, *Whh1hi, *Whh1lo, *XChi, *XClo;
    cudaGetSymbolAddress((void**)&G0, d_G0);
    cudaGetSymbolAddress((void**)&G1, d_G1);
    cudaGetSymbolAddress((void**)&Z, d_Zb);
    cudaGetSymbolAddress((void**)&hhi, d_hhi);
    cudaGetSymbolAddress((void**)&hlo, d_hlo);
    cudaGetSymbolAddress((void**)&A0hi, d_A0hi);
    cudaGetSymbolAddress((void**)&A0lo, d_A0lo);
    cudaGetSymbolAddress((void**)&Wih0hi, d_Wih0hi);
    cudaGetSymbolAddress((void**)&Wih0lo, d_Wih0lo);
    cudaGetSymbolAddress((void**)&Whh0hi, d_Whh0hi);
    cudaGetSymbolAddress((void**)&Whh0lo, d_Whh0lo);
    cudaGetSymbolAddress((void**)&Wih1hi, d_Wih1hi);
    cudaGetSymbolAddress((void**)&Wih1lo, d_Wih1lo);
    cudaGetSymbolAddress((void**)&Whh1hi, d_Whh1hi);
    cudaGetSymbolAddress((void**)&Whh1lo, d_Whh1lo);
    cudaGetSymbolAddress((void**)&XChi, d_XChi);
    cudaGetSymbolAddress((void**)&XClo, d_XClo);

    const int SCAN_SMEM = (16896 * 2 + 9216 + 2048 * 2 + 512 * 2) * 4;  // 192512 B
    static int attr_set = 0;
    if (!attr_set) {
        cudaFuncSetAttribute(scan_kernel, cudaFuncAttributeMaxDynamicSharedMemorySize, SCAN_SMEM);
        attr_set = 1;
    }

    // 1) input split
    split_x_kernel<<<(S_ * B_ * (E_ / 4) + 255) / 256, 256>>>(x, A0hi, A0lo);
    // 2) fused weight splits (float4 units)
    {
        int n0 = 2 * G_ * E_ / 4, n1 = 2 * G_ * H_ / 4, n2 = 2 * G_ * 2 * H_ / 4, n3 = 2 * G_ * H_ / 4;
        int total = n0 + n1 + n2 + n3;
        split_weights_kernel<<<(total + 255) / 256, 256>>>(
            w_ih0, Wih0hi, Wih0lo, n0,
            w_hh0, Whh0hi, Whh0lo, n1,
            w_ih1, Wih1hi, Wih1lo, n2,
            w_hh1, Whh1hi, Whh1lo, n3);
    }

    // 3) layer-0 input projection
    {
        dim3 grid(G_ / 128, (S_ * B_) / 64, 2);
        gemm3_tf32_kernel<64, 128><<<grid, 256>>>(A0hi, A0lo, Wih0hi, Wih0lo, G0,
                                                  S_ * B_, G_, E_,
                                                  0L, (long)G_ * E_, (long)S_ * B_ * G_);
    }
    // 4) LN
    ln_rows_kernel<<<2 * S_ * B_, 256>>>(G0, ln_ih0_g, ln_ih0_b, S_ * B_);

    // 5) layer-0 persistent scan
    scan_kernel<<<NCTA, 256, SCAN_SMEM>>>(Whh0hi, Whh0lo,
                                          G0, (long)B_ * G_, (long)S_ * B_ * G_,
                                          ln_hh0_g, ln_hh0_b, ln_ho0_g, ln_ho0_b,
                                          Z, hhi, hlo, 0, out);

    // 6) layer-1 input (constant over time due to aliasing bug)
    build_xc_kernel<<<(B_ * 2 * H_ + 255) / 256, 256>>>(hhi, hlo, XChi, XClo);
    {
        dim3 grid(G_ / 128, 1, 2);
        gemm3_tf32_kernel<64, 128><<<grid, 256>>>(XChi, XClo, Wih1hi, Wih1lo, G1,
                                                  B_, G_, 2 * H_,
                                                  0L, (long)G_ * 2 * H_, (long)B_ * G_);
    }
    ln_rows_kernel<<<2 * B_, 256>>>(G1, ln_ih1_g, ln_ih1_b, B_);

    // 7) layer-1 persistent scan
    scan_kernel<<<NCTA, 256, SCAN_SMEM>>>(Whh1hi, Whh1lo,
                                          G1, 0L, (long)B_ * G_,
                                          ln_hh1_g, ln_hh1_b, ln_ho1_g, ln_ho1_b,
                                          Z, hhi, hlo, 1, out);
}

// round 11
// speedup vs baseline: 3.2930x; 1.1159x over previous
#include <cuda_runtime.h>
#include <cuda_bf16.h>
#include <mma.h>

using namespace nvcuda;

#define B_ 64
#define S_ 48
#define E_ 512
#define H_ 512
#define G_ 2048  /* 4H */
#define NCTA 128

// ---------------- scratch (static device memory; no allocations) ----------------
__device__ __align__(16) float d_G0[2 * S_ * B_ * G_];   // LN(x@Wih0^T), both dirs
__device__ __align__(16) float d_G1[2 * B_ * G_];        // LN(xc@Wih1^T)
__device__ __align__(16) float d_Zb[2 * B_ * G_];        // per-step h@Whh^T
// tf32 hi/lo pairs stored as float
__device__ __align__(16) float d_hhi[2 * B_ * H_], d_hlo[2 * B_ * H_];
__device__ __align__(16) float d_A0hi[S_ * B_ * E_], d_A0lo[S_ * B_ * E_];
__device__ __align__(16) float d_Wih0hi[2 * G_ * E_], d_Wih0lo[2 * G_ * E_];
__device__ __align__(16) float d_Whh0hi[2 * G_ * H_], d_Whh0lo[2 * G_ * H_];
__device__ __align__(16) float d_Wih1hi[2 * G_ * 2 * H_], d_Wih1lo[2 * G_ * 2 * H_];
__device__ __align__(16) float d_Whh1hi[2 * G_ * H_], d_Whh1lo[2 * G_ * H_];
__device__ __align__(16) float d_XChi[B_ * 2 * H_], d_XClo[B_ * 2 * H_];

// grid-barrier state
__device__ unsigned d_bar_count = 0;
__device__ unsigned d_bar_gen = 0;

// ---------------- helpers ----------------
__device__ __forceinline__ float f2tf32(float x) {
    unsigned r;
    asm("cvt.rna.tf32.f32 %0, %1;" : "=r"(r) : "f"(x));
    return __uint_as_float(r);
}

__device__ __forceinline__ double block_reduce_d(double a, double* buf) {
    __syncthreads();
    for (int o = 16; o > 0; o >>= 1)
        a += __shfl_down_sync(0xffffffffu, a, o);
    int w = threadIdx.x >> 5;
    if ((threadIdx.x & 31) == 0) buf[w] = a;
    __syncthreads();
    int nw = (blockDim.x + 31) >> 5;
    double s = 0.0;
    for (int i = 0; i < nw; i++) s += buf[i];
    return s;
}

__device__ __forceinline__ float sigmoidf_(float x) { return 1.f / (1.f + expf(-x)); }

// CG-style grid barrier: intra-CTA sync, thread0 fence+atomic+tight poll.
__device__ __forceinline__ void grid_barrier() {
    __syncthreads();
    if (threadIdx.x == 0) {
        __threadfence();
        unsigned gen = *((volatile unsigned*)&d_bar_gen);
        unsigned old = atomicAdd(&d_bar_count, 1u);
        if (old == NCTA - 1) {
            d_bar_count = 0;
            __threadfence();
            atomicAdd(&d_bar_gen, 1u);
        } else {
            while (*((volatile unsigned*)&d_bar_gen) == gen) { }
        }
    }
    __syncthreads();
}

// ---------------- fused split kernel (fp32 -> tf32 hi/lo, float4-vectorized) ----------------
__device__ __forceinline__ void split4(float4 v, float4& h, float4& l) {
    h.x = f2tf32(v.x); l.x = f2tf32(v.x - h.x);
    h.y = f2tf32(v.y); l.y = f2tf32(v.y - h.y);
    h.z = f2tf32(v.z); l.z = f2tf32(v.z - h.z);
    h.w = f2tf32(v.w); l.w = f2tf32(v.w - h.w);
}

// one kernel: x-transpose-split + all 4 weight splits (sizes in float4 units)
__global__ void fused_split_kernel(const float* __restrict__ x, float* __restrict__ xhi, float* __restrict__ xlo, int nx,
                                   const float* __restrict__ s0, float* __restrict__ h0, float* __restrict__ l0, int n0,
                                   const float* __restrict__ s1, float* __restrict__ h1, float* __restrict__ l1, int n1,
                                   const float* __restrict__ s2, float* __restrict__ h2, float* __restrict__ l2, int n2,
                                   const float* __restrict__ s3, float* __restrict__ h3, float* __restrict__ l3, int n3) {
    int i = blockIdx.x * blockDim.x + threadIdx.x;  // float4 index
    if (i < nx) {
        // x[b][s][e] -> A[(s*B+b)][e]
        int e4 = i % (E_ / 4);
        int r = i / (E_ / 4);
        int s = r / B_;
        int b = r % B_;
        float4 v = *(const float4*)(x + ((size_t)b * S_ + s) * E_ + e4 * 4);
        float4 hv, lv;
        split4(v, hv, lv);
        ((float4*)xhi)[i] = hv;
        ((float4*)xlo)[i] = lv;
        return;
    }
    i -= nx;
    const float* s; float* h; float* l;
    if (i < n0) { s = s0; h = h0; l = l0; }
    else if ((i -= n0) < n1) { s = s1; h = h1; l = l1; }
    else if ((i -= n1) < n2) { s = s2; h = h2; l = l2; }
    else if ((i -= n2) < n3) { s = s3; h = h3; l = l3; }
    else return;
    float4 v = ((const float4*)s)[i], hv, lv;
    split4(v, hv, lv);
    ((float4*)h)[i] = hv;
    ((float4*)l)[i] = lv;
}

// xc[b][k] = concat(h_dir0[b], h_dir1[b]) tf32 hi/lo
__global__ void build_xc_kernel(const float* __restrict__ hhi, const float* __restrict__ hlo,
                                float* __restrict__ xchi, float* __restrict__ xclo) {
    int i = blockIdx.x * blockDim.x + threadIdx.x;
    if (i < B_ * 2 * H_) {
        int k = i % (2 * H_);
        int b = i / (2 * H_);
        int d = k / H_;
        int j = k % H_;
        size_t src = (size_t)(d * B_ + b) * H_ + j;
        xchi[i] = hhi[src];
        xclo[i] = hlo[src];
    }
}

// ---------------- 3-term split-tf32 GEMM (input projections only) ----------------
template <int BM, int BN>
__global__ void __launch_bounds__(256, 1)
gemm3_tf32_kernel(const float* __restrict__ Ahi, const float* __restrict__ Alo,
                  const float* __restrict__ Whi, const float* __restrict__ Wlo,
                  float* __restrict__ C, int M, int N, int K,
                  long aBatch, long wBatch, long cBatch) {
    constexpr int BK = 16;
    constexpr int LDS = BK + 4;
    const int z = blockIdx.z;
    Ahi += (size_t)z * aBatch; Alo += (size_t)z * aBatch;
    Whi += (size_t)z * wBatch; Wlo += (size_t)z * wBatch;
    C += (size_t)z * cBatch;
    const int m0 = blockIdx.y * BM, n0 = blockIdx.x * BN;
    const int tid = threadIdx.x;

    __shared__ __align__(16) float sAh[BM][LDS];
    __shared__ __align__(16) float sAl[BM][LDS];
    __shared__ __align__(16) float sBh[BN][LDS];
    __shared__ __align__(16) float sBl[BN][LDS];

    wmma::fragment<wmma::accumulator, 16, 16, 8, float> accM0[2][2], accM1[2][2], accX[2][2];
#pragma unroll
    for (int i = 0; i < 2; i++)
#pragma unroll
        for (int j = 0; j < 2; j++) {
            wmma::fill_fragment(accM0[i][j], 0.f);
            wmma::fill_fragment(accM1[i][j], 0.f);
            wmma::fill_fragment(accX[i][j], 0.f);
        }

    const int wid = tid >> 5;
    const int wm = wid >> 2;
    const int wn = wid & 3;
    const int Khalf = K >> 1;

    for (int k0 = 0; k0 < K; k0 += BK) {
#pragma unroll
        for (int i = tid; i < BM * (BK / 4); i += 256) {
            int r = i / (BK / 4), q = i % (BK / 4);
            size_t g = (size_t)(m0 + r) * K + k0 + q * 4;
            *(float4*)&sAh[r][q * 4] = *(const float4*)(Ahi + g);
            *(float4*)&sAl[r][q * 4] = *(const float4*)(Alo + g);
        }
#pragma unroll
        for (int i = tid; i < BN * (BK / 4); i += 256) {
            int r = i / (BK / 4), q = i % (BK / 4);
            size_t g = (size_t)(n0 + r) * K + k0 + q * 4;
            *(float4*)&sBh[r][q * 4] = *(const float4*)(Whi + g);
            *(float4*)&sBl[r][q * 4] = *(const float4*)(Wlo + g);
        }
        __syncthreads();
        const bool firstHalf = (k0 < Khalf);
#pragma unroll
        for (int kk = 0; kk < BK; kk += 8) {
            wmma::fragment<wmma::matrix_a, 16, 16, 8, wmma::precision::tf32, wmma::row_major> ah[2], al[2];
            wmma::fragment<wmma::matrix_b, 16, 16, 8, wmma::precision::tf32, wmma::col_major> bh[2], bl[2];
#pragma unroll
            for (int i = 0; i < 2; i++) {
                wmma::load_matrix_sync(ah[i], &sAh[wm * 32 + i * 16][kk], LDS);
                wmma::load_matrix_sync(al[i], &sAl[wm * 32 + i * 16][kk], LDS);
                wmma::load_matrix_sync(bh[i], &sBh[wn * 32 + i * 16][kk], LDS);
                wmma::load_matrix_sync(bl[i], &sBl[wn * 32 + i * 16][kk], LDS);
            }
            if (firstHalf) {
#pragma unroll
                for (int i = 0; i < 2; i++)
#pragma unroll
                    for (int j = 0; j < 2; j++)
                        wmma::mma_sync(accM0[i][j], ah[i], bh[j], accM0[i][j]);
            } else {
#pragma unroll
                for (int i = 0; i < 2; i++)
#pragma unroll
                    for (int j = 0; j < 2; j++)
                        wmma::mma_sync(accM1[i][j], ah[i], bh[j], accM1[i][j]);
            }
#pragma unroll
            for (int i = 0; i < 2; i++)
#pragma unroll
                for (int j = 0; j < 2; j++) {
                    wmma::mma_sync(accX[i][j], ah[i], bl[j], accX[i][j]);
                    wmma::mma_sync(accX[i][j], al[i], bh[j], accX[i][j]);
                }
        }
        __syncthreads();
    }
#pragma unroll
    for (int i = 0; i < 2; i++)
#pragma unroll
        for (int j = 0; j < 2; j++) {
#pragma unroll
            for (int e = 0; e < accM0[i][j].num_elements; e++)
                accM0[i][j].x[e] = (float)(((double)accM0[i][j].x[e] + (double)accM1[i][j].x[e])
                                           + (double)accX[i][j].x[e]);
            wmma::store_matrix_sync(&C[(size_t)(m0 + wm * 32 + i * 16) * N + n0 + wn * 32 + j * 16],
                                    accM0[i][j], N, wmma::mem_row_major);
        }
}

// ---------------- row LayerNorm: fp32 elementwise, fp64 cross-thread reductions ----------------
__global__ void ln_rows_kernel(float* __restrict__ data, const float* __restrict__ gamma,
                               const float* __restrict__ beta, int rowsPerDir) {
    __shared__ double red[8];
    const int width = G_;
    long row = blockIdx.x;
    int d = (int)(row / rowsPerDir);
    float* p = data + row * (long)width;
    const int tid = threadIdx.x;
    float v[8];
    float ps = 0.f;
#pragma unroll
    for (int q = 0; q < 8; q++) {
        v[q] = p[tid + q * 256];
        ps += v[q];
    }
    double s = block_reduce_d((double)ps, red);
    float mu = (float)(s / width);
    float psq = 0.f;
#pragma unroll
    for (int q = 0; q < 8; q++) {
        float dv = v[q] - mu;
        psq = fmaf(dv, dv, psq);
    }
    double sq = block_reduce_d((double)psq, red);
    float rstd = (float)rsqrt(sq / width + 1e-5);
    const float* g = gamma + (size_t)d * width;
    const float* be = beta + (size_t)d * width;
#pragma unroll
    for (int q = 0; q < 8; q++) {
        int j = tid + q * 256;
        p[j] = fmaf((v[q] - mu) * rstd, g[j], be[j]);
    }
}

// ================= persistent scan kernel =================
// 128 CTAs x 256 threads, 1 CTA/SM.
__global__ void __launch_bounds__(256, 1)
scan_kernel(const float* __restrict__ Whh_hi, const float* __restrict__ Whh_lo,
            const float* __restrict__ gih, long gihTime, long gihDir,
            const float* __restrict__ g_hh, const float* __restrict__ b_hh,
            const float* __restrict__ g_ho, const float* __restrict__ b_ho,
            float* __restrict__ Z, float* __restrict__ hhi, float* __restrict__ hlo,
            int writeOut, float* __restrict__ out) {
    extern __shared__ float sm[];
    float* sWh = sm;                          // 16*32*33 = 16896
    float* sWl = sWh + 16896;                 // 16896
    float* sA = sWl + 16896;                  // 2 buf * 2 (hi,lo) * 2304
    float* sGhh = sA + 9216;                  // 2048
    float* sBhh = sGhh + 2048;                // 2048
    float* sGho = sBhh + 2048;                // 512
    float* sBho = sGho + 512;                 // 512
    __shared__ double red[8];

    const int tid = threadIdx.x;
    const int cta = blockIdx.x;
    const int d = cta >> 6;                   // direction
    const int n0 = (cta & 63) * 32;           // gemm column block
    const int cb = cta & 63;                  // cell batch row
    const int wid = tid >> 5;
    const int wm = wid >> 1;                  // 0..3 (16-row m slice)
    const int wn = wid & 1;                   // 0..1 (16-col n slice)

    // ---- one-time fills ----
    {
        const float* wh = Whh_hi + ((size_t)d * G_ + n0) * H_;
        const float* wl = Whh_lo + ((size_t)d * G_ + n0) * H_;
        for (int i = tid; i < 32 * H_; i += 256) {
            int r = i >> 9, k = i & 511;
            int kb = k >> 5, kk = k & 31;
            int off = kb * (32 * 33) + r * 33 + kk;
            sWh[off] = __ldg(wh + (size_t)r * H_ + k);
            sWl[off] = __ldg(wl + (size_t)r * H_ + k);
        }
    }
    for (int i = tid; i < G_; i += 256) {
        sGhh[i] = __ldg(g_hh + (size_t)d * G_ + i);
        sBhh[i] = __ldg(b_hh + (size_t)d * G_ + i);
    }
    for (int i = tid; i < H_; i += 256) {
        sGho[i] = __ldg(g_ho + (size_t)d * H_ + i);
        sBho[i] = __ldg(b_ho + (size_t)d * H_ + i);
    }
    {
        float* ph = hhi + (size_t)cta * H_;
        float* pl = hlo + (size_t)cta * H_;
        for (int i = tid; i < H_; i += 256) { ph[i] = 0.f; pl[i] = 0.f; }
    }
    double c_reg0 = 0.0, c_reg1 = 0.0;        // persistent fp64 cell state
    grid_barrier();

    const int r0 = tid >> 3, q0 = (tid & 7) * 4;
    const int r1 = (tid + 256) >> 3, q1 = q0;

    for (int t = 0; t < S_; t++) {
        // prefetch gi for cell phase
        const int tt = (d == 0) ? t : (S_ - 1 - t);
        const float* gi = gih + (size_t)d * gihDir + (size_t)tt * gihTime + (size_t)cb * G_;
        float gir[8];
#pragma unroll
        for (int q = 0; q < 8; q++) gir[q] = __ldg(gi + tid + q * 256);

        // ======== GEMM phase ========
        wmma::fragment<wmma::accumulator, 16, 16, 8, float> accM0, accM1, accX1, accX2;
        wmma::fill_fragment(accM0, 0.f);
        wmma::fill_fragment(accM1, 0.f);
        wmma::fill_fragment(accX1, 0.f);
        wmma::fill_fragment(accX2, 0.f);

        float4 rh0 = __ldcg((const float4*)(hhi + (size_t)(d * B_ + r0) * H_ + q0));
        float4 rh1 = __ldcg((const float4*)(hhi + (size_t)(d * B_ + r1) * H_ + q1));
        float4 rl0 = __ldcg((const float4*)(hlo + (size_t)(d * B_ + r0) * H_ + q0));
        float4 rl1 = __ldcg((const float4*)(hlo + (size_t)(d * B_ + r1) * H_ + q1));

#pragma unroll 4
        for (int kb = 0; kb < 16; kb++) {
            float* bAh = sA + (kb & 1) * 4608;
            float* bAl = bAh + 2304;
            *(float4*)&bAh[r0 * 36 + q0] = rh0;
            *(float4*)&bAh[r1 * 36 + q1] = rh1;
            *(float4*)&bAl[r0 * 36 + q0] = rl0;
            *(float4*)&bAl[r1 * 36 + q1] = rl1;
            __syncthreads();
            if (kb < 15) {
                int k0n = (kb + 1) * 32;
                rh0 = __ldcg((const float4*)(hhi + (size_t)(d * B_ + r0) * H_ + k0n + q0));
                rh1 = __ldcg((const float4*)(hhi + (size_t)(d * B_ + r1) * H_ + k0n + q1));
                rl0 = __ldcg((const float4*)(hlo + (size_t)(d * B_ + r0) * H_ + k0n + q0));
                rl1 = __ldcg((const float4*)(hlo + (size_t)(d * B_ + r1) * H_ + k0n + q1));
            }
            const float* bWh = sWh + kb * (32 * 33) + (wn * 16) * 33;
            const float* bWl = sWl + kb * (32 * 33) + (wn * 16) * 33;
#pragma unroll
            for (int kk = 0; kk < 32; kk += 8) {
                wmma::fragment<wmma::matrix_a, 16, 16, 8, wmma::precision::tf32, wmma::row_major> ah, al;
                wmma::fragment<wmma::matrix_b, 16, 16, 8, wmma::precision::tf32, wmma::col_major> bh, bl;
                wmma::load_matrix_sync(ah, &bAh[(wm * 16) * 36 + kk], 36);
                wmma::load_matrix_sync(al, &bAl[(wm * 16) * 36 + kk], 36);
                wmma::load_matrix_sync(bh, bWh + kk, 33);
                wmma::load_matrix_sync(bl, bWl + kk, 33);
                if (kb < 8) wmma::mma_sync(accM0, ah, bh, accM0);
                else        wmma::mma_sync(accM1, ah, bh, accM1);
                wmma::mma_sync(accX1, ah, bl, accX1);
                wmma::mma_sync(accX2, al, bh, accX2);
            }
        }
#pragma unroll
        for (int e = 0; e < accM0.num_elements; e++)
            accM0.x[e] = (float)(((double)accM0.x[e] + (double)accM1.x[e])
                                 + ((double)accX1.x[e] + (double)accX2.x[e]));
        wmma::store_matrix_sync(Z + (size_t)(d * B_ + wm * 16) * G_ + n0 + wn * 16,
                                accM0, G_, wmma::mem_row_major);

        grid_barrier();

        // ======== cell phase (row cta = (d, cb)); fp32 elementwise, fp64 reductions ========
        {
            const float* z = Z + (size_t)cta * G_;
            float zr[8];
            float ps = 0.f;
#pragma unroll
            for (int q = 0; q < 8; q++) {
                zr[q] = __ldcg(z + tid + q * 256);
                ps += zr[q];
            }
            double s = block_reduce_d((double)ps, red);
            float mu = (float)(s / G_);
            float psq = 0.f;
#pragma unroll
            for (int q = 0; q < 8; q++) {
                float dv = zr[q] - mu;
                psq = fmaf(dv, dv, psq);
            }
            double sq = block_reduce_d((double)psq, red);
            float rstd = (float)rsqrt(sq / G_ + 1e-5);

            double cn_st[2];
            float o_st[2];
            double ps2 = 0.0;
#pragma unroll
            for (int cnt = 0; cnt < 2; cnt++) {
                int j = tid + cnt * 256;
                float ai = fmaf((zr[cnt]     - mu) * rstd, sGhh[j],            sBhh[j])            + gir[cnt];
                float af = fmaf((zr[cnt + 2] - mu) * rstd, sGhh[j + H_],       sBhh[j + H_])       + gir[cnt + 2];
                float ao = fmaf((zr[cnt + 4] - mu) * rstd, sGhh[j + 2 * H_],   sBhh[j + 2 * H_])   + gir[cnt + 4];
                float ag = fmaf((zr[cnt + 6] - mu) * rstd, sGhh[j + 3 * H_],   sBhh[j + 3 * H_])   + gir[cnt + 6];
                float ig = sigmoidf_(ai);
                float fg = sigmoidf_(af);
                float og = sigmoidf_(ao);
                float gg = tanhf(ag);
                double cold = (cnt == 0) ? c_reg0 : c_reg1;
                double cn = (double)fg * cold + (double)(ig * gg);
                if (cnt == 0) c_reg0 = cn; else c_reg1 = cn;
                cn_st[cnt] = cn;
                o_st[cnt] = og;
                ps2 += cn;
            }
            double s2 = block_reduce_d(ps2, red);
            double muc = s2 / H_;
            double psq2 = 0.0;
#pragma unroll
            for (int cnt = 0; cnt < 2; cnt++) {
                double dv = cn_st[cnt] - muc;
                psq2 += dv * dv;
            }
            double sq2 = block_reduce_d(psq2, red);
            float rstdc = (float)rsqrt(sq2 / H_ + 1e-5);

#pragma unroll
            for (int cnt = 0; cnt < 2; cnt++) {
                int j = tid + cnt * 256;
                float dvf = (float)(cn_st[cnt] - muc);
                float lnc = fmaf(dvf * rstdc, sGho[j], sBho[j]);
                float hn = o_st[cnt] * tanhf(lnc);
                size_t hi_ = (size_t)cta * H_ + j;
                float hb = f2tf32(hn);
                hhi[hi_] = hb;
                hlo[hi_] = f2tf32(hn - hb);
                if (writeOut && t == S_ - 1)
                    out[(size_t)cb * (2 * H_) + (size_t)d * H_ + j] = hn;
            }
        }
        grid_barrier();
    }
}

// ---------------- host orchestration ----------------
extern "C" void kernel_launch(void* const* d_in, const int* in_sizes, int n_in,
                              void* d_out, int out_size) {
    const float* x = (const float*)d_in[0];
    // d_in[1] = text_length (unused)
    const float* w_ih0 = (const float*)d_in[2];
    const float* w_hh0 = (const float*)d_in[3];
    const float* ln_ih0_g = (const float*)d_in[4];
    const float* ln_ih0_b = (const float*)d_in[5];
    const float* ln_hh0_g = (const float*)d_in[6];
    const float* ln_hh0_b = (const float*)d_in[7];
    const float* ln_ho0_g = (const float*)d_in[8];
    const float* ln_ho0_b = (const float*)d_in[9];
    const float* w_ih1 = (const float*)d_in[10];
    const float* w_hh1 = (const float*)d_in[11];
    const float* ln_ih1_g = (const float*)d_in[12];
    const float* ln_ih1_b = (const float*)d_in[13];
    const float* ln_hh1_g = (const float*)d_in[14];
    const float* ln_hh1_b = (const float*)d_in[15];
    const float* ln_ho1_g = (const float*)d_in[16];
    const float* ln_ho1_b = (const float*)d_in[17];
    float* out = (float*)d_out;

    float *G0, *G1, *Z;
    float *hhi, *hlo, *A0hi, *A0lo, *Wih0hi, *Wih0lo, *Whh0hi, *Whh0lo;
    float *Wih1hi, *Wih1lo, *Whh1hi, *Whh1lo, *XChi, *XClo;
    cudaGetSymbolAddress((void**)&G0, d_G0);
    cudaGetSymbolAddress((void**)&G1, d_G1);
    cudaGetSymbolAddress((void**)&Z, d_Zb);
    cudaGetSymbolAddress((void**)&hhi, d_hhi);
    cudaGetSymbolAddress((void**)&hlo, d_hlo);
    cudaGetSymbolAddress((void**)&A0hi, d_A0hi);
    cudaGetSymbolAddress((void**)&A0lo, d_A0lo);
    cudaGetSymbolAddress((void**)&Wih0hi, d_Wih0hi);
    cudaGetSymbolAddress((void**)&Wih0lo, d_Wih0lo);
    cudaGetSymbolAddress((void**)&Whh0hi, d_Whh0hi);
    cudaGetSymbolAddress((void**)&Whh0lo, d_Whh0lo);
    cudaGetSymbolAddress((void**)&Wih1hi, d_Wih1hi);
    cudaGetSymbolAddress((void**)&Wih1lo, d_Wih1lo);
    cudaGetSymbolAddress((void**)&Whh1hi, d_Whh1hi);
    cudaGetSymbolAddress((void**)&Whh1lo, d_Whh1lo);
    cudaGetSymbolAddress((void**)&XChi, d_XChi);
    cudaGetSymbolAddress((void**)&XClo, d_XClo);

    const int SCAN_SMEM = (16896 * 2 + 9216 + 2048 * 2 + 512 * 2) * 4;  // 192512 B
    static int attr_set = 0;
    if (!attr_set) {
        cudaFuncSetAttribute(scan_kernel, cudaFuncAttributeMaxDynamicSharedMemorySize, SCAN_SMEM);
        attr_set = 1;
    }

    // 1) fused splits (x transpose-split + 4 weight splits), float4 units
    {
        int nx = S_ * B_ * E_ / 4;
        int n0 = 2 * G_ * E_ / 4, n1 = 2 * G_ * H_ / 4, n2 = 2 * G_ * 2 * H_ / 4, n3 = 2 * G_ * H_ / 4;
        int total = nx + n0 + n1 + n2 + n3;
        fused_split_kernel<<<(total + 255) / 256, 256>>>(
            x, A0hi, A0lo, nx,
            w_ih0, Wih0hi, Wih0lo, n0,
            w_hh0, Whh0hi, Whh0lo, n1,
            w_ih1, Wih1hi, Wih1lo, n2,
            w_hh1, Whh1hi, Whh1lo, n3);
    }

    // 2) layer-0 input projection
    {
        dim3 grid(G_ / 128, (S_ * B_) / 64, 2);
        gemm3_tf32_kernel<64, 128><<<grid, 256>>>(A0hi, A0lo, Wih0hi, Wih0lo, G0,
                                                  S_ * B_, G_, E_,
                                                  0L, (long)G_ * E_, (long)S_ * B_ * G_);
    }
    // 3) LN
    ln_rows_kernel<<<2 * S_ * B_, 256>>>(G0, ln_ih0_g, ln_ih0_b, S_ * B_);

    // 4) layer-0 persistent scan
    scan_kernel<<<NCTA, 256, SCAN_SMEM>>>(Whh0hi, Whh0lo,
                                          G0, (long)B_ * G_, (long)S_ * B_ * G_,
                                          ln_hh0_g, ln_hh0_b, ln_ho0_g, ln_ho0_b,
                                          Z, hhi, hlo, 0, out);

    // 5) layer-1 input (constant over time due to aliasing bug)
    build_xc_kernel<<<(B_ * 2 * H_ + 255) / 256, 256>>>(hhi, hlo, XChi, XClo);
    {
        dim3 grid(G_ / 128, 1, 2);
        gemm3_tf32_kernel<64, 128><<<grid, 256>>>(XChi, XClo, Wih1hi, Wih1lo, G1,
                                                  B_, G_, 2 * H_,
                                                  0L, (long)G_ * 2 * H_, (long)B_ * G_);
    }
    ln_rows_kernel<<<2 * B_, 256>>>(G1, ln_ih1_g, ln_ih1_b, B_);

    // 6) layer-1 persistent scan
    scan_kernel<<<NCTA, 256, SCAN_SMEM>>>(Whh1hi, Whh1lo,
                                          G1, 0L, (long)B_ * G_,
                                          ln_hh1_g, ln_hh1_b, ln_ho1_g, ln_ho1_b,
                                          Z, hhi, hlo, 1, out);
}